// round 1
// baseline (speedup 1.0000x reference)
#include <cuda_runtime.h>
#include <cuda_bf16.h>
#include <math.h>

// ---------------- problem constants ----------------
#define Bq    8
#define Tq    16
#define HID   4096
#define HQ    64
#define HKV   8
#define Dh    64
#define QMULT 8            // HQ / HKV
#define TC    4096
#define TTOT  (TC + Tq)    // 4112
#define WIN   128
#define NKEY  (WIN + 1)    // 129 keys in window
#define QKVD  5120         // D*(HQ+2*HKV)
#define NROW  (Bq * Tq)    // 128
#define SM_SCALE 0.125f
#define THETA 150000.0

#define OUT_ELEMS   ((size_t)NROW * HID)                 // 524288
#define KV_ELEMS    ((size_t)Bq * TTOT * HKV * Dh)       // 16842752

// ---------------- scratch ----------------
__device__ float g_h[NROW * HID];
__device__ float g_qkv[NROW * QKVD];
__device__ float g_attn[NROW * HID];

// ---------------- KV cache copy ----------------
// cache (B, TC, HKV, D) -> out K/V (B, TTOT, HKV, D), rows [0, TC)
__global__ __launch_bounds__(256) void copy_kv_kernel(
    const float4* __restrict__ ck, const float4* __restrict__ cv,
    float4* __restrict__ Kout, float4* __restrict__ Vout)
{
    const int perb = TC * HKV * Dh / 4;        // 524288 vec4 per batch
    const int dstb = TTOT * HKV * Dh / 4;      // 526336
    const int total = Bq * perb;               // 4194304
    for (int i = blockIdx.x * blockDim.x + threadIdx.x; i < total;
         i += gridDim.x * blockDim.x) {
        int b = i / perb;
        int r = i - b * perb;
        int dst = b * dstb + r;
        Kout[dst] = ck[i];
        Vout[dst] = cv[i];
    }
}

// ---------------- rmsnorm ----------------
__global__ __launch_bounds__(256) void rmsnorm_kernel(
    const float* __restrict__ x, const float* __restrict__ w, float* __restrict__ h)
{
    int row = blockIdx.x;
    const float* xr = x + (size_t)row * HID;
    float* hr = h + (size_t)row * HID;
    float ss = 0.f;
    for (int i = threadIdx.x; i < HID; i += 256) {
        float v = xr[i];
        ss += v * v;
    }
    __shared__ float red[256];
    red[threadIdx.x] = ss;
    __syncthreads();
    for (int s = 128; s > 0; s >>= 1) {
        if (threadIdx.x < s) red[threadIdx.x] += red[threadIdx.x + s];
        __syncthreads();
    }
    float inv = rsqrtf(red[0] / (float)HID + 1e-5f);
    for (int i = threadIdx.x; i < HID; i += 256)
        hr[i] = xr[i] * inv * w[i];
}

// ---------------- SGEMM  C[M,N] = A[M,K] * W[N,K]^T + bias (+ resid) ----------------
__global__ __launch_bounds__(256) void sgemm_nt_kernel(
    const float* __restrict__ A, const float* __restrict__ W,
    const float* __restrict__ bias, const float* __restrict__ resid,
    float* __restrict__ C, int M, int N, int K)
{
    const int BM = 64, BN = 64, BK = 32;
    __shared__ float As[BK][BM];
    __shared__ float Ws[BK][BN];
    int bm = blockIdx.y * BM;
    int bn = blockIdx.x * BN;
    int tid = threadIdx.x;
    int tx = tid & 15;
    int ty = tid >> 4;
    float acc[4][4] = {};

    const float* Ab = A + (size_t)bm * K;
    const float* Wb = W + (size_t)bn * K;

    for (int k0 = 0; k0 < K; k0 += BK) {
#pragma unroll
        for (int s = 0; s < 2; s++) {
            int fi = tid + s * 256;      // 0..511
            int row = fi >> 3;           // 0..63
            int kq = (fi & 7) << 2;      // 0..28 step 4
            float4 av = *(const float4*)(Ab + (size_t)row * K + k0 + kq);
            float4 wv = *(const float4*)(Wb + (size_t)row * K + k0 + kq);
            As[kq + 0][row] = av.x; As[kq + 1][row] = av.y;
            As[kq + 2][row] = av.z; As[kq + 3][row] = av.w;
            Ws[kq + 0][row] = wv.x; Ws[kq + 1][row] = wv.y;
            Ws[kq + 2][row] = wv.z; Ws[kq + 3][row] = wv.w;
        }
        __syncthreads();
#pragma unroll
        for (int kk = 0; kk < BK; kk++) {
            float a[4], b[4];
#pragma unroll
            for (int i = 0; i < 4; i++) a[i] = As[kk][ty * 4 + i];
#pragma unroll
            for (int j = 0; j < 4; j++) b[j] = Ws[kk][tx * 4 + j];
#pragma unroll
            for (int i = 0; i < 4; i++)
#pragma unroll
                for (int j = 0; j < 4; j++)
                    acc[i][j] = fmaf(a[i], b[j], acc[i][j]);
        }
        __syncthreads();
    }

#pragma unroll
    for (int i = 0; i < 4; i++) {
        int m = bm + ty * 4 + i;
#pragma unroll
        for (int j = 0; j < 4; j++) {
            int n = bn + tx * 4 + j;
            float v = acc[i][j] + bias[n];
            if (resid) v += resid[(size_t)m * N + n];
            C[(size_t)m * N + n] = v;
        }
    }
}

// ---------------- RoPE on q (in-place) + roped k / raw v appended to K/V ----------------
__global__ __launch_bounds__(256) void rope_split_kernel(
    float* __restrict__ qkv, float* __restrict__ Kout, float* __restrict__ Vout)
{
    int row = blockIdx.x;               // 0..127
    int b = row >> 4;
    int t = row & 15;
    int pos = TC + t;
    float* q = qkv + (size_t)row * QKVD;
    const double lg = log(THETA);

    // q pairs: 64 heads * 32 pairs = 2048 ; k pairs: 8 heads * 32 = 256
    for (int p = threadIdx.x; p < 2048 + 256; p += blockDim.x) {
        int head, j;
        float* basep;
        bool isq = (p < 2048);
        if (isq) {
            head = p >> 5; j = p & 31;
            basep = q + head * 64;
        } else {
            int pp = p - 2048;
            head = pp >> 5; j = pp & 31;
            basep = q + HQ * Dh + head * 64;
        }
        float invf = (float)exp(-(double)(2 * j) / 64.0 * lg);
        float ang = (float)pos * invf;                 // f32 product, like jax
        float c = cosf(ang), s = sinf(ang);
        float x1 = basep[j], x2 = basep[j + 32];
        float r1 = x1 * c - x2 * s;
        float r2 = x2 * c + x1 * s;
        if (isq) {
            basep[j] = r1;
            basep[j + 32] = r2;
        } else {
            size_t o = ((((size_t)b * TTOT) + pos) * HKV + head) * Dh;
            Kout[o + j] = r1;
            Kout[o + j + 32] = r2;
        }
    }
    // v copy: 512 floats
    for (int i = threadIdx.x; i < HKV * Dh; i += blockDim.x) {
        size_t o = (((size_t)b * TTOT) + pos) * HKV * Dh + i;
        Vout[o] = q[(HQ + HKV) * Dh + i];
    }
}

// ---------------- windowed attention with sink ----------------
// grid (HKV, T, B), 256 threads (8 warps = QMULT heads)
__global__ __launch_bounds__(256) void attn_kernel(
    const float* __restrict__ qkv, const float* __restrict__ Kout,
    const float* __restrict__ Vout, const float* __restrict__ sinks,
    float* __restrict__ attn)
{
    int hkv = blockIdx.x;
    int t = blockIdx.y;
    int b = blockIdx.z;
    int row = b * Tq + t;
    int k0 = TC + t - WIN;              // first key index (>=0)

    __shared__ float sKV[NKEY * 65];    // padded rows (65) to kill bank conflicts
    __shared__ float sQ[QMULT * Dh];
    __shared__ float sW[QMULT * 132];

    int tid = threadIdx.x;
    int warp = tid >> 5, lane = tid & 31;

    // load q (already roped): heads hkv*8..hkv*8+7
    for (int i = tid; i < QMULT * Dh; i += 256)
        sQ[i] = qkv[(size_t)row * QKVD + hkv * (QMULT * Dh) + i];

    // load K window
    for (int i = tid; i < NKEY * Dh; i += 256) {
        int j = i >> 6, d = i & 63;
        sKV[j * 65 + d] = Kout[((((size_t)b * TTOT) + k0 + j) * HKV + hkv) * Dh + d];
    }
    __syncthreads();

    // logits: warp 'warp' handles q-head (hkv*8 + warp)
    float lgv[5];
    float mx = -INFINITY;
#pragma unroll
    for (int i = 0; i < 5; i++) {
        int j = lane + i * 32;
        float acc = -INFINITY;
        if (j < NKEY) {
            acc = 0.f;
            const float* qq = &sQ[warp * Dh];
            const float* kk = &sKV[j * 65];
#pragma unroll 8
            for (int d = 0; d < Dh; d++) acc = fmaf(qq[d], kk[d], acc);
            acc *= SM_SCALE;
        }
        lgv[i] = acc;
        mx = fmaxf(mx, acc);
    }
#pragma unroll
    for (int o = 16; o > 0; o >>= 1)
        mx = fmaxf(mx, __shfl_xor_sync(0xffffffffu, mx, o));
    float snk = sinks[hkv * QMULT + warp];
    mx = fmaxf(mx, snk);

    float se = 0.f;
#pragma unroll
    for (int i = 0; i < 5; i++) {
        int j = lane + i * 32;
        if (j < NKEY) {
            lgv[i] = expf(lgv[i] - mx);
            se += lgv[i];
        }
    }
#pragma unroll
    for (int o = 16; o > 0; o >>= 1)
        se += __shfl_xor_sync(0xffffffffu, se, o);
    float denom = se + expf(snk - mx);
    float rdenom = 1.f / denom;
#pragma unroll
    for (int i = 0; i < 5; i++) {
        int j = lane + i * 32;
        if (j < NKEY) sW[warp * 132 + j] = lgv[i] * rdenom;
    }
    __syncthreads();   // all warps done reading sKV (K) and writing sW

    // load V window (reuse sKV)
    for (int i = tid; i < NKEY * Dh; i += 256) {
        int j = i >> 6, d = i & 63;
        sKV[j * 65 + d] = Vout[((((size_t)b * TTOT) + k0 + j) * HKV + hkv) * Dh + d];
    }
    __syncthreads();

    // out: each lane owns dims lane and lane+32
    float a0 = 0.f, a1 = 0.f;
#pragma unroll 4
    for (int j = 0; j < NKEY; j++) {
        float w = sW[warp * 132 + j];
        a0 = fmaf(w, sKV[j * 65 + lane], a0);
        a1 = fmaf(w, sKV[j * 65 + 32 + lane], a1);
    }
    size_t ob = (size_t)row * HID + (hkv * QMULT + warp) * Dh;
    attn[ob + lane] = a0;
    attn[ob + 32 + lane] = a1;
}

// ---------------- launch ----------------
extern "C" void kernel_launch(void* const* d_in, const int* in_sizes, int n_in,
                              void* d_out, int out_size)
{
    // input order: x, cache_k, cache_v, [cache_position], sinks, norm_w,
    //              qkv_w, qkv_b, out_w, out_b
    int sh = 0;
    if (n_in >= 10) sh = 1;                    // cache_position present at idx 3
    else if (n_in == 9 && in_sizes[3] == 1) sh = 1;

    const float* x       = (const float*)d_in[0];
    const float* cache_k = (const float*)d_in[1];
    const float* cache_v = (const float*)d_in[2];
    const float* sinks   = (const float*)d_in[3 + sh];
    const float* norm_w  = (const float*)d_in[4 + sh];
    const float* qkv_w   = (const float*)d_in[5 + sh];
    const float* qkv_b   = (const float*)d_in[6 + sh];
    const float* out_w   = (const float*)d_in[7 + sh];
    const float* out_b   = (const float*)d_in[8 + sh];

    float* out  = (float*)d_out;
    float* Kout = out + OUT_ELEMS;
    float* Vout = Kout + KV_ELEMS;

    float *hp, *qkvp, *attnp;
    cudaGetSymbolAddress((void**)&hp, g_h);
    cudaGetSymbolAddress((void**)&qkvp, g_qkv);
    cudaGetSymbolAddress((void**)&attnp, g_attn);

    // 1) copy cached K/V into output
    copy_kv_kernel<<<4096, 256>>>((const float4*)cache_k, (const float4*)cache_v,
                                  (float4*)Kout, (float4*)Vout);
    // 2) rmsnorm
    rmsnorm_kernel<<<NROW, 256>>>(x, norm_w, hp);
    // 3) qkv gemm
    {
        dim3 grid(QKVD / 64, NROW / 64);
        sgemm_nt_kernel<<<grid, 256>>>(hp, qkv_w, qkv_b, nullptr, qkvp,
                                       NROW, QKVD, HID);
    }
    // 4) rope + scatter new k/v
    rope_split_kernel<<<NROW, 256>>>(qkvp, Kout, Vout);
    // 5) attention
    {
        dim3 grid(HKV, Tq, Bq);
        attn_kernel<<<grid, 256>>>(qkvp, Kout, Vout, sinks, attnp);
    }
    // 6) out gemm + bias + residual
    {
        dim3 grid(HID / 64, NROW / 64);
        sgemm_nt_kernel<<<grid, 256>>>(attnp, out_w, out_b, x, out,
                                       NROW, HID, HID);
    }
}

// round 3
// speedup vs baseline: 3.2724x; 3.2724x over previous
#include <cuda_runtime.h>
#include <cuda_bf16.h>
#include <cstdint>
#include <math.h>

// ---------------- problem constants ----------------
#define Bq    8
#define Tq    16
#define HID   4096
#define HQ    64
#define HKV   8
#define Dh    64
#define QMULT 8            // HQ / HKV
#define TC    4096
#define TTOT  (TC + Tq)    // 4112
#define WIN   128
#define NKEY  (WIN + 1)    // 129 keys in window
#define QKVD  5120         // D*(HQ+2*HKV)
#define NROW  (Bq * Tq)    // 128
#define SM_SCALE 0.125f

#define OUT_ELEMS   ((size_t)NROW * HID)                 // 524288
#define KV_ELEMS    ((size_t)Bq * TTOT * HKV * Dh)       // 16842752

// ---------------- scratch ----------------
__device__ float g_h[NROW * HID];
__device__ float g_qkv[NROW * QKVD];
__device__ float g_attn[NROW * HID];
__device__ float g_part[4 * NROW * QKVD];   // split-K partials (max 4 x 128 x 5120)

// ---------------- KV cache copy ----------------
__global__ __launch_bounds__(256) void copy_kv_kernel(
    const float4* __restrict__ ck, const float4* __restrict__ cv,
    float4* __restrict__ Kout, float4* __restrict__ Vout)
{
    const int perb = TC * HKV * Dh / 4;        // 524288 vec4 per batch
    const int dstb = TTOT * HKV * Dh / 4;      // 526336
    const int total = Bq * perb;               // 4194304
    for (int i = blockIdx.x * blockDim.x + threadIdx.x; i < total;
         i += gridDim.x * blockDim.x) {
        int b = i / perb;
        int r = i - b * perb;
        int dst = b * dstb + r;
        Kout[dst] = ck[i];
        Vout[dst] = cv[i];
    }
}

// ---------------- rmsnorm ----------------
__global__ __launch_bounds__(256) void rmsnorm_kernel(
    const float* __restrict__ x, const float* __restrict__ w, float* __restrict__ h)
{
    int row = blockIdx.x;
    const float* xr = x + (size_t)row * HID;
    float* hr = h + (size_t)row * HID;
    float ss = 0.f;
    for (int i = threadIdx.x; i < HID; i += 256) {
        float v = xr[i];
        ss += v * v;
    }
    __shared__ float red[256];
    red[threadIdx.x] = ss;
    __syncthreads();
    for (int s = 128; s > 0; s >>= 1) {
        if (threadIdx.x < s) red[threadIdx.x] += red[threadIdx.x + s];
        __syncthreads();
    }
    float inv = rsqrtf(red[0] / (float)HID + 1e-5f);
    for (int i = threadIdx.x; i < HID; i += 256)
        hr[i] = xr[i] * inv * w[i];
}

// ---------------- tf32 helpers ----------------
__device__ __forceinline__ float to_tf32(float x) {
    uint32_t u;
    asm("cvt.rna.tf32.f32 %0, %1;" : "=r"(u) : "f"(x));
    return __uint_as_float(u);
}

__device__ __forceinline__ void mma_tf32(float c[4], const uint32_t a[4],
                                         const uint32_t b[2]) {
    asm volatile(
        "mma.sync.aligned.m16n8k8.row.col.f32.tf32.tf32.f32 "
        "{%0,%1,%2,%3}, {%4,%5,%6,%7}, {%8,%9}, {%0,%1,%2,%3};\n"
        : "+f"(c[0]), "+f"(c[1]), "+f"(c[2]), "+f"(c[3])
        : "r"(a[0]), "r"(a[1]), "r"(a[2]), "r"(a[3]), "r"(b[0]), "r"(b[1]));
}

// ---------------- tf32 split-K GEMM ----------------
// C_partial[split][m][n] = A[m,:]*W[n,:]^T over this split's K-range.
// M = 128 fixed. BM=128, BN=128, BK=32. 256 threads = 8 warps (4m x 2n),
// warp tile 32m x 64n. grid = (N/128, S).
#define SMTILE (128 * 36)
__global__ __launch_bounds__(256) void gemm_tf32_splitk(
    const float* __restrict__ A, const float* __restrict__ W,
    float* __restrict__ P, int N, int K)
{
    extern __shared__ float sm[];
    float* Abase = sm;                 // [2][128][36]
    float* Wbase = sm + 2 * SMTILE;    // [2][128][36]

    int tid = threadIdx.x;
    int wid = tid >> 5, lane = tid & 31;
    int wm = (wid >> 1) * 32;          // warp m offset (0,32,64,96)
    int wn = (wid & 1) * 64;           // warp n offset (0,64)
    int g = lane >> 2, t = lane & 3;

    int bn = blockIdx.x * 128;
    int kb = K >> 5;                   // total BK iters
    int S = gridDim.y;
    int per = (kb + S - 1) / S;
    int it0 = blockIdx.y * per;
    int it1 = min(it0 + per, kb);

    int row[4], qq[4];
#pragma unroll
    for (int s = 0; s < 4; s++) {
        int v = tid + s * 256;
        row[s] = v >> 3;               // 0..127
        qq[s] = (v & 7) << 2;          // 0..28 step 4
    }

    float acc[2][8][4];
#pragma unroll
    for (int mi = 0; mi < 2; mi++)
#pragma unroll
        for (int ni = 0; ni < 8; ni++)
#pragma unroll
            for (int r = 0; r < 4; r++) acc[mi][ni][r] = 0.f;

    float4 ra[4], rw[4];

#define LDTILE(IT)                                                          \
    {                                                                       \
        int k0 = (IT) << 5;                                                 \
        _Pragma("unroll") for (int s = 0; s < 4; s++) {                     \
            ra[s] = *(const float4*)(A + (size_t)row[s] * K + k0 + qq[s]);  \
            rw[s] = *(const float4*)(W + (size_t)(bn + row[s]) * K + k0 + qq[s]); \
        }                                                                   \
    }

#define STTILE(BUF)                                                         \
    {                                                                       \
        float* Ab = Abase + (BUF) * SMTILE;                                 \
        float* Wb = Wbase + (BUF) * SMTILE;                                 \
        _Pragma("unroll") for (int s = 0; s < 4; s++) {                     \
            float4 a = ra[s], w = rw[s];                                    \
            a.x = to_tf32(a.x); a.y = to_tf32(a.y);                         \
            a.z = to_tf32(a.z); a.w = to_tf32(a.w);                         \
            w.x = to_tf32(w.x); w.y = to_tf32(w.y);                         \
            w.z = to_tf32(w.z); w.w = to_tf32(w.w);                         \
            *(float4*)(Ab + row[s] * 36 + qq[s]) = a;                       \
            *(float4*)(Wb + row[s] * 36 + qq[s]) = w;                       \
        }                                                                   \
    }

    LDTILE(it0);
    STTILE(0);
    __syncthreads();

    int buf = 0;
    for (int it = it0; it < it1; ++it) {
        bool more = (it + 1 < it1);
        if (more) LDTILE(it + 1);

        const float* Ab = Abase + buf * SMTILE;
        const float* Wb = Wbase + buf * SMTILE;
#pragma unroll
        for (int ks = 0; ks < 4; ks++) {
            int kk = ks * 8;
            uint32_t af[2][4], bf[8][2];
#pragma unroll
            for (int mi = 0; mi < 2; mi++) {
                int r = wm + mi * 16;
                af[mi][0] = __float_as_uint(Ab[(r + g) * 36 + kk + t]);
                af[mi][1] = __float_as_uint(Ab[(r + g + 8) * 36 + kk + t]);
                af[mi][2] = __float_as_uint(Ab[(r + g) * 36 + kk + t + 4]);
                af[mi][3] = __float_as_uint(Ab[(r + g + 8) * 36 + kk + t + 4]);
            }
#pragma unroll
            for (int ni = 0; ni < 8; ni++) {
                int c = wn + ni * 8 + g;
                bf[ni][0] = __float_as_uint(Wb[c * 36 + kk + t]);
                bf[ni][1] = __float_as_uint(Wb[c * 36 + kk + t + 4]);
            }
#pragma unroll
            for (int mi = 0; mi < 2; mi++)
#pragma unroll
                for (int ni = 0; ni < 8; ni++)
                    mma_tf32(acc[mi][ni], af[mi], bf[ni]);
        }
        if (more) STTILE(buf ^ 1);
        __syncthreads();
        buf ^= 1;
    }

    // epilogue: write partials
    float* Pb = P + (size_t)blockIdx.y * NROW * N;
#pragma unroll
    for (int mi = 0; mi < 2; mi++) {
        int r0 = wm + mi * 16 + g;
#pragma unroll
        for (int ni = 0; ni < 8; ni++) {
            int c = bn + wn + ni * 8 + 2 * t;
            *(float2*)(Pb + (size_t)r0 * N + c) =
                make_float2(acc[mi][ni][0], acc[mi][ni][1]);
            *(float2*)(Pb + (size_t)(r0 + 8) * N + c) =
                make_float2(acc[mi][ni][2], acc[mi][ni][3]);
        }
    }
}

// ---------------- split-K reduce (+bias, +optional residual) ----------------
__global__ __launch_bounds__(256) void reduce_splitk(
    const float* __restrict__ P, const float* __restrict__ bias,
    const float* __restrict__ resid, float* __restrict__ C, int N, int S)
{
    int i = blockIdx.x * 256 + threadIdx.x;    // float4 index
    int total = (NROW * N) >> 2;
    if (i >= total) return;
    const float4* P4 = (const float4*)P;
    float4 a = P4[i];
    for (int s = 1; s < S; s++) {
        float4 b = P4[i + (size_t)s * total];
        a.x += b.x; a.y += b.y; a.z += b.z; a.w += b.w;
    }
    float4 bb = ((const float4*)bias)[i % (N >> 2)];
    a.x += bb.x; a.y += bb.y; a.z += bb.z; a.w += bb.w;
    if (resid) {
        float4 rr = ((const float4*)resid)[i];
        a.x += rr.x; a.y += rr.y; a.z += rr.z; a.w += rr.w;
    }
    ((float4*)C)[i] = a;
}

// ---------------- RoPE on q (in-place) + roped k / raw v appended ----------------
__global__ __launch_bounds__(256) void rope_split_kernel(
    float* __restrict__ qkv, float* __restrict__ Kout, float* __restrict__ Vout)
{
    int row = blockIdx.x;               // 0..127
    int b = row >> 4;
    int t = row & 15;
    int pos = TC + t;
    float* q = qkv + (size_t)row * QKVD;
    const float NEG_L2T_32 = -0.537331431f;   // -log2(150000)/32

    for (int p = threadIdx.x; p < 2048 + 256; p += blockDim.x) {
        int head, j;
        float* basep;
        bool isq = (p < 2048);
        if (isq) {
            head = p >> 5; j = p & 31;
            basep = q + head * 64;
        } else {
            int pp = p - 2048;
            head = pp >> 5; j = pp & 31;
            basep = q + HQ * Dh + head * 64;
        }
        float invf = exp2f((float)j * NEG_L2T_32);
        float ang = (float)pos * invf;
        float c = cosf(ang), s = sinf(ang);
        float x1 = basep[j], x2 = basep[j + 32];
        float r1 = x1 * c - x2 * s;
        float r2 = x2 * c + x1 * s;
        if (isq) {
            basep[j] = r1;
            basep[j + 32] = r2;
        } else {
            size_t o = ((((size_t)b * TTOT) + pos) * HKV + head) * Dh;
            Kout[o + j] = r1;
            Kout[o + j + 32] = r2;
        }
    }
    for (int i = threadIdx.x; i < HKV * Dh; i += blockDim.x) {
        size_t o = (((size_t)b * TTOT) + pos) * HKV * Dh + i;
        Vout[o] = q[(HQ + HKV) * Dh + i];
    }
}

// ---------------- windowed attention with sink ----------------
__global__ __launch_bounds__(256) void attn_kernel(
    const float* __restrict__ qkv, const float* __restrict__ Kout,
    const float* __restrict__ Vout, const float* __restrict__ sinks,
    float* __restrict__ attn)
{
    int hkv = blockIdx.x;
    int t = blockIdx.y;
    int b = blockIdx.z;
    int row = b * Tq + t;
    int k0 = TC + t - WIN;

    __shared__ float sKV[NKEY * 65];
    __shared__ float sQ[QMULT * Dh];
    __shared__ float sW[QMULT * 132];

    int tid = threadIdx.x;
    int warp = tid >> 5, lane = tid & 31;

    for (int i = tid; i < QMULT * Dh; i += 256)
        sQ[i] = qkv[(size_t)row * QKVD + hkv * (QMULT * Dh) + i];

    for (int i = tid; i < NKEY * Dh; i += 256) {
        int j = i >> 6, d = i & 63;
        sKV[j * 65 + d] = Kout[((((size_t)b * TTOT) + k0 + j) * HKV + hkv) * Dh + d];
    }
    __syncthreads();

    float lgv[5];
    float mx = -INFINITY;
#pragma unroll
    for (int i = 0; i < 5; i++) {
        int j = lane + i * 32;
        float acc = -INFINITY;
        if (j < NKEY) {
            acc = 0.f;
            const float* qq = &sQ[warp * Dh];
            const float* kk = &sKV[j * 65];
#pragma unroll 8
            for (int d = 0; d < Dh; d++) acc = fmaf(qq[d], kk[d], acc);
            acc *= SM_SCALE;
        }
        lgv[i] = acc;
        mx = fmaxf(mx, acc);
    }
#pragma unroll
    for (int o = 16; o > 0; o >>= 1)
        mx = fmaxf(mx, __shfl_xor_sync(0xffffffffu, mx, o));
    float snk = sinks[hkv * QMULT + warp];
    mx = fmaxf(mx, snk);

    float se = 0.f;
#pragma unroll
    for (int i = 0; i < 5; i++) {
        int j = lane + i * 32;
        if (j < NKEY) {
            lgv[i] = expf(lgv[i] - mx);
            se += lgv[i];
        }
    }
#pragma unroll
    for (int o = 16; o > 0; o >>= 1)
        se += __shfl_xor_sync(0xffffffffu, se, o);
    float denom = se + expf(snk - mx);
    float rdenom = 1.f / denom;
#pragma unroll
    for (int i = 0; i < 5; i++) {
        int j = lane + i * 32;
        if (j < NKEY) sW[warp * 132 + j] = lgv[i] * rdenom;
    }
    __syncthreads();

    for (int i = tid; i < NKEY * Dh; i += 256) {
        int j = i >> 6, d = i & 63;
        sKV[j * 65 + d] = Vout[((((size_t)b * TTOT) + k0 + j) * HKV + hkv) * Dh + d];
    }
    __syncthreads();

    float a0 = 0.f, a1 = 0.f;
#pragma unroll 4
    for (int j = 0; j < NKEY; j++) {
        float w = sW[warp * 132 + j];
        a0 = fmaf(w, sKV[j * 65 + lane], a0);
        a1 = fmaf(w, sKV[j * 65 + 32 + lane], a1);
    }
    size_t ob = (size_t)row * HID + (hkv * QMULT + warp) * Dh;
    attn[ob + lane] = a0;
    attn[ob + 32 + lane] = a1;
}

// ---------------- launch ----------------
extern "C" void kernel_launch(void* const* d_in, const int* in_sizes, int n_in,
                              void* d_out, int out_size)
{
    int sh = 0;
    if (n_in >= 10) sh = 1;
    else if (n_in == 9 && in_sizes[3] == 1) sh = 1;

    const float* x       = (const float*)d_in[0];
    const float* cache_k = (const float*)d_in[1];
    const float* cache_v = (const float*)d_in[2];
    const float* sinks   = (const float*)d_in[3 + sh];
    const float* norm_w  = (const float*)d_in[4 + sh];
    const float* qkv_w   = (const float*)d_in[5 + sh];
    const float* qkv_b   = (const float*)d_in[6 + sh];
    const float* out_w   = (const float*)d_in[7 + sh];
    const float* out_b   = (const float*)d_in[8 + sh];

    float* out  = (float*)d_out;
    float* Kout = out + OUT_ELEMS;
    float* Vout = Kout + KV_ELEMS;

    float *hp, *qkvp, *attnp, *partp;
    cudaGetSymbolAddress((void**)&hp, g_h);
    cudaGetSymbolAddress((void**)&qkvp, g_qkv);
    cudaGetSymbolAddress((void**)&attnp, g_attn);
    cudaGetSymbolAddress((void**)&partp, g_part);

    static int smem_set = 0;
    if (!smem_set) {
        cudaFuncSetAttribute(gemm_tf32_splitk,
                             cudaFuncAttributeMaxDynamicSharedMemorySize,
                             4 * SMTILE * (int)sizeof(float));
        smem_set = 1;
    }
    const int smem_bytes = 4 * SMTILE * (int)sizeof(float);   // 73728

    // 1) copy cached K/V into output
    copy_kv_kernel<<<4096, 256>>>((const float4*)cache_k, (const float4*)cache_v,
                                  (float4*)Kout, (float4*)Vout);
    // 2) rmsnorm
    rmsnorm_kernel<<<NROW, 256>>>(x, norm_w, hp);
    // 3) qkv gemm (tf32, split-K=3) + reduce
    {
        dim3 grid(QKVD / 128, 3);
        gemm_tf32_splitk<<<grid, 256, smem_bytes>>>(hp, qkv_w, partp, QKVD, HID);
        reduce_splitk<<<(NROW * QKVD / 4 + 255) / 256, 256>>>(
            partp, qkv_b, nullptr, qkvp, QKVD, 3);
    }
    // 4) rope + scatter new k/v
    rope_split_kernel<<<NROW, 256>>>(qkvp, Kout, Vout);
    // 5) attention
    {
        dim3 grid(HKV, Tq, Bq);
        attn_kernel<<<grid, 256>>>(qkvp, Kout, Vout, sinks, attnp);
    }
    // 6) out gemm (tf32, split-K=4) + reduce (bias + residual)
    {
        dim3 grid(HID / 128, 4);
        gemm_tf32_splitk<<<grid, 256, smem_bytes>>>(attnp, out_w, partp, HID, HID);
        reduce_splitk<<<(NROW * HID / 4 + 255) / 256, 256>>>(
            partp, out_b, x, out, HID, 4);
    }
}

// round 4
// speedup vs baseline: 3.3670x; 1.0289x over previous
#include <cuda_runtime.h>
#include <cuda_bf16.h>
#include <cstdint>
#include <math.h>

// ---------------- problem constants ----------------
#define Bq    8
#define Tq    16
#define HID   4096
#define HQ    64
#define HKV   8
#define Dh    64
#define QMULT 8            // HQ / HKV
#define TC    4096
#define TTOT  (TC + Tq)    // 4112
#define WIN   128
#define NKEY  (WIN + 1)    // 129 keys in window
#define QKVD  5120         // D*(HQ+2*HKV)
#define NROW  (Bq * Tq)    // 128
#define SM_SCALE 0.125f

#define OUT_ELEMS   ((size_t)NROW * HID)                 // 524288
#define KV_ELEMS    ((size_t)Bq * TTOT * HKV * Dh)       // 16842752

// ---------------- scratch ----------------
__device__ float g_h[NROW * HID];
__device__ float g_qkv[NROW * QKVD];
__device__ float g_attn[NROW * HID];
__device__ float g_part[4 * NROW * QKVD];   // split-K partials
__device__ float g_knew[NROW * HKV * Dh];   // new roped K rows (b,t,hkv,d)
__device__ float g_vnew[NROW * HKV * Dh];   // new V rows

// ---------------- KV cache copy (independent; overlapped) ----------------
__global__ __launch_bounds__(256) void copy_kv_kernel(
    const float4* __restrict__ ck, const float4* __restrict__ cv,
    float4* __restrict__ Kout, float4* __restrict__ Vout)
{
    const int perb = TC * HKV * Dh / 4;        // 524288 vec4 per batch
    const int dstb = TTOT * HKV * Dh / 4;      // 526336
    const int total = Bq * perb;               // 4194304
    for (int i = blockIdx.x * blockDim.x + threadIdx.x; i < total;
         i += gridDim.x * blockDim.x) {
        int b = i / perb;
        int r = i - b * perb;
        int dst = b * dstb + r;
        Kout[dst] = ck[i];
        Vout[dst] = cv[i];
    }
}

// ---------------- rmsnorm ----------------
__global__ __launch_bounds__(256) void rmsnorm_kernel(
    const float* __restrict__ x, const float* __restrict__ w, float* __restrict__ h)
{
    int row = blockIdx.x;
    const float* xr = x + (size_t)row * HID;
    float* hr = h + (size_t)row * HID;
    float ss = 0.f;
    for (int i = threadIdx.x; i < HID; i += 256) {
        float v = xr[i];
        ss += v * v;
    }
    __shared__ float red[256];
    red[threadIdx.x] = ss;
    __syncthreads();
    for (int s = 128; s > 0; s >>= 1) {
        if (threadIdx.x < s) red[threadIdx.x] += red[threadIdx.x + s];
        __syncthreads();
    }
    float inv = rsqrtf(red[0] / (float)HID + 1e-5f);
    for (int i = threadIdx.x; i < HID; i += 256)
        hr[i] = xr[i] * inv * w[i];
}

// ---------------- tf32 helpers ----------------
__device__ __forceinline__ float to_tf32(float x) {
    uint32_t u;
    asm("cvt.rna.tf32.f32 %0, %1;" : "=r"(u) : "f"(x));
    return __uint_as_float(u);
}

__device__ __forceinline__ void mma_tf32(float c[4], const uint32_t a[4],
                                         const uint32_t b[2]) {
    asm volatile(
        "mma.sync.aligned.m16n8k8.row.col.f32.tf32.tf32.f32 "
        "{%0,%1,%2,%3}, {%4,%5,%6,%7}, {%8,%9}, {%0,%1,%2,%3};\n"
        : "+f"(c[0]), "+f"(c[1]), "+f"(c[2]), "+f"(c[3])
        : "r"(a[0]), "r"(a[1]), "r"(a[2]), "r"(a[3]), "r"(b[0]), "r"(b[1]));
}

// ---------------- tf32 split-K GEMM ----------------
#define SMTILE (128 * 36)
__global__ __launch_bounds__(256) void gemm_tf32_splitk(
    const float* __restrict__ A, const float* __restrict__ W,
    float* __restrict__ P, int N, int K)
{
    extern __shared__ float sm[];
    float* Abase = sm;                 // [2][128][36]
    float* Wbase = sm + 2 * SMTILE;    // [2][128][36]

    int tid = threadIdx.x;
    int wid = tid >> 5, lane = tid & 31;
    int wm = (wid >> 1) * 32;
    int wn = (wid & 1) * 64;
    int g = lane >> 2, t = lane & 3;

    int bn = blockIdx.x * 128;
    int kb = K >> 5;
    int S = gridDim.y;
    int per = (kb + S - 1) / S;
    int it0 = blockIdx.y * per;
    int it1 = min(it0 + per, kb);

    int row[4], qq[4];
#pragma unroll
    for (int s = 0; s < 4; s++) {
        int v = tid + s * 256;
        row[s] = v >> 3;
        qq[s] = (v & 7) << 2;
    }

    float acc[2][8][4];
#pragma unroll
    for (int mi = 0; mi < 2; mi++)
#pragma unroll
        for (int ni = 0; ni < 8; ni++)
#pragma unroll
            for (int r = 0; r < 4; r++) acc[mi][ni][r] = 0.f;

    float4 ra[4], rw[4];

#define LDTILE(IT)                                                          \
    {                                                                       \
        int k0 = (IT) << 5;                                                 \
        _Pragma("unroll") for (int s = 0; s < 4; s++) {                     \
            ra[s] = *(const float4*)(A + (size_t)row[s] * K + k0 + qq[s]);  \
            rw[s] = *(const float4*)(W + (size_t)(bn + row[s]) * K + k0 + qq[s]); \
        }                                                                   \
    }

#define STTILE(BUF)                                                         \
    {                                                                       \
        float* Ab = Abase + (BUF) * SMTILE;                                 \
        float* Wb = Wbase + (BUF) * SMTILE;                                 \
        _Pragma("unroll") for (int s = 0; s < 4; s++) {                     \
            float4 a = ra[s], w = rw[s];                                    \
            a.x = to_tf32(a.x); a.y = to_tf32(a.y);                         \
            a.z = to_tf32(a.z); a.w = to_tf32(a.w);                         \
            w.x = to_tf32(w.x); w.y = to_tf32(w.y);                         \
            w.z = to_tf32(w.z); w.w = to_tf32(w.w);                         \
            *(float4*)(Ab + row[s] * 36 + qq[s]) = a;                       \
            *(float4*)(Wb + row[s] * 36 + qq[s]) = w;                       \
        }                                                                   \
    }

    LDTILE(it0);
    STTILE(0);
    __syncthreads();

    int buf = 0;
    for (int it = it0; it < it1; ++it) {
        bool more = (it + 1 < it1);
        if (more) LDTILE(it + 1);

        const float* Ab = Abase + buf * SMTILE;
        const float* Wb = Wbase + buf * SMTILE;
#pragma unroll
        for (int ks = 0; ks < 4; ks++) {
            int kk = ks * 8;
            uint32_t af[2][4], bf[8][2];
#pragma unroll
            for (int mi = 0; mi < 2; mi++) {
                int r = wm + mi * 16;
                af[mi][0] = __float_as_uint(Ab[(r + g) * 36 + kk + t]);
                af[mi][1] = __float_as_uint(Ab[(r + g + 8) * 36 + kk + t]);
                af[mi][2] = __float_as_uint(Ab[(r + g) * 36 + kk + t + 4]);
                af[mi][3] = __float_as_uint(Ab[(r + g + 8) * 36 + kk + t + 4]);
            }
#pragma unroll
            for (int ni = 0; ni < 8; ni++) {
                int c = wn + ni * 8 + g;
                bf[ni][0] = __float_as_uint(Wb[c * 36 + kk + t]);
                bf[ni][1] = __float_as_uint(Wb[c * 36 + kk + t + 4]);
            }
#pragma unroll
            for (int mi = 0; mi < 2; mi++)
#pragma unroll
                for (int ni = 0; ni < 8; ni++)
                    mma_tf32(acc[mi][ni], af[mi], bf[ni]);
        }
        if (more) STTILE(buf ^ 1);
        __syncthreads();
        buf ^= 1;
    }

    float* Pb = P + (size_t)blockIdx.y * NROW * N;
#pragma unroll
    for (int mi = 0; mi < 2; mi++) {
        int r0 = wm + mi * 16 + g;
#pragma unroll
        for (int ni = 0; ni < 8; ni++) {
            int c = bn + wn + ni * 8 + 2 * t;
            *(float2*)(Pb + (size_t)r0 * N + c) =
                make_float2(acc[mi][ni][0], acc[mi][ni][1]);
            *(float2*)(Pb + (size_t)(r0 + 8) * N + c) =
                make_float2(acc[mi][ni][2], acc[mi][ni][3]);
        }
    }
}

// ---------------- fused QKV reduce(+bias) + RoPE + K/V scatter ----------------
// one block per row; stages the 5120-wide row in smem, ropes q/k, writes:
//   qkv (roped q), Kout+knew (roped k), Vout+vnew (v)
__global__ __launch_bounds__(256) void reduce_qkv_rope(
    const float* __restrict__ P, const float* __restrict__ bias,
    float* __restrict__ qkv, float* __restrict__ Kout, float* __restrict__ Vout,
    float* __restrict__ knew, float* __restrict__ vnew)
{
    __shared__ float srow[QKVD];
    int row = blockIdx.x;
    int b = row >> 4, t = row & 15, pos = TC + t;
    const int RV4 = QKVD / 4;                  // 1280
    const size_t SPLIT = (size_t)NROW * RV4;   // vec4 per split
    const float4* P4 = (const float4*)P;
    const float4* B4 = (const float4*)bias;

#pragma unroll
    for (int k = 0; k < 5; k++) {
        int i = threadIdx.x + k * 256;
        size_t off = (size_t)row * RV4 + i;
        float4 a = P4[off];
        float4 p1 = P4[off + SPLIT];
        float4 p2 = P4[off + 2 * SPLIT];
        float4 bb = B4[i];
        a.x += p1.x + p2.x + bb.x;
        a.y += p1.y + p2.y + bb.y;
        a.z += p1.z + p2.z + bb.z;
        a.w += p1.w + p2.w + bb.w;
        *(float4*)&srow[i * 4] = a;
    }
    __syncthreads();

    const float NEG_L2T_32 = -0.537331431f;    // -log2(150000)/32
    for (int p = threadIdx.x; p < 2048 + 256; p += 256) {
        bool isq = (p < 2048);
        int pp = isq ? p : p - 2048;
        int head = pp >> 5, j = pp & 31;
        int base = (isq ? head * 64 : HQ * Dh + head * 64);
        float invf = exp2f((float)j * NEG_L2T_32);
        float ang = (float)pos * invf;
        float c = cosf(ang), s = sinf(ang);
        float x1 = srow[base + j], x2 = srow[base + j + 32];
        float r1 = x1 * c - x2 * s;
        float r2 = x2 * c + x1 * s;
        if (isq) {
            qkv[(size_t)row * QKVD + base + j] = r1;
            qkv[(size_t)row * QKVD + base + j + 32] = r2;
        } else {
            size_t o = ((((size_t)b * TTOT) + pos) * HKV + head) * Dh;
            Kout[o + j] = r1;
            Kout[o + j + 32] = r2;
            size_t on = (((size_t)row * HKV) + head) * Dh;
            knew[on + j] = r1;
            knew[on + j + 32] = r2;
        }
    }
    for (int i = threadIdx.x; i < HKV * Dh; i += 256) {
        float v = srow[(HQ + HKV) * Dh + i];
        Vout[(((size_t)b * TTOT) + pos) * HKV * Dh + i] = v;
        vnew[(size_t)row * HKV * Dh + i] = v;
    }
}

// ---------------- OUT reduce: 4 splits + bias + residual (compile-time N) ----------------
__global__ __launch_bounds__(256) void reduce_out_kernel(
    const float* __restrict__ P, const float* __restrict__ bias,
    const float* __restrict__ x, float* __restrict__ out)
{
    int i = blockIdx.x * 256 + threadIdx.x;    // vec4 idx, total 131072
    const int TOT = NROW * HID / 4;
    const float4* P4 = (const float4*)P;
    float4 a = P4[i];
    float4 p1 = P4[i + TOT];
    float4 p2 = P4[i + 2 * TOT];
    float4 p3 = P4[i + 3 * TOT];
    float4 bb = ((const float4*)bias)[i & (HID / 4 - 1)];
    float4 rr = ((const float4*)x)[i];
    a.x += p1.x + p2.x + p3.x + bb.x + rr.x;
    a.y += p1.y + p2.y + p3.y + bb.y + rr.y;
    a.z += p1.z + p2.z + p3.z + bb.z + rr.z;
    a.w += p1.w + p2.w + p3.w + bb.w + rr.w;
    ((float4*)out)[i] = a;
}

// ---------------- windowed attention with sink (reads cache directly) ----------------
__global__ __launch_bounds__(256) void attn_kernel(
    const float* __restrict__ qkv,
    const float* __restrict__ cache_k, const float* __restrict__ cache_v,
    const float* __restrict__ knew, const float* __restrict__ vnew,
    const float* __restrict__ sinks, float* __restrict__ attn)
{
    int hkv = blockIdx.x;
    int t = blockIdx.y;
    int b = blockIdx.z;
    int row = b * Tq + t;
    int k0 = TC + t - WIN;

    __shared__ float sKV[NKEY * 65];
    __shared__ float sQ[QMULT * Dh];
    __shared__ float sW[QMULT * 132];

    int tid = threadIdx.x;
    int warp = tid >> 5, lane = tid & 31;

    for (int i = tid; i < QMULT * Dh; i += 256)
        sQ[i] = qkv[(size_t)row * QKVD + hkv * (QMULT * Dh) + i];

    for (int i = tid; i < NKEY * Dh; i += 256) {
        int j = i >> 6, d = i & 63;
        int kj = k0 + j;
        float v;
        if (kj < TC)
            v = cache_k[(((size_t)b * TC + kj) * HKV + hkv) * Dh + d];
        else
            v = knew[(((size_t)b * Tq + (kj - TC)) * HKV + hkv) * Dh + d];
        sKV[j * 65 + d] = v;
    }
    __syncthreads();

    float lgv[5];
    float mx = -INFINITY;
#pragma unroll
    for (int i = 0; i < 5; i++) {
        int j = lane + i * 32;
        float acc = -INFINITY;
        if (j < NKEY) {
            acc = 0.f;
            const float* qq = &sQ[warp * Dh];
            const float* kk = &sKV[j * 65];
#pragma unroll 8
            for (int d = 0; d < Dh; d++) acc = fmaf(qq[d], kk[d], acc);
            acc *= SM_SCALE;
        }
        lgv[i] = acc;
        mx = fmaxf(mx, acc);
    }
#pragma unroll
    for (int o = 16; o > 0; o >>= 1)
        mx = fmaxf(mx, __shfl_xor_sync(0xffffffffu, mx, o));
    float snk = sinks[hkv * QMULT + warp];
    mx = fmaxf(mx, snk);

    float se = 0.f;
#pragma unroll
    for (int i = 0; i < 5; i++) {
        int j = lane + i * 32;
        if (j < NKEY) {
            lgv[i] = expf(lgv[i] - mx);
            se += lgv[i];
        }
    }
#pragma unroll
    for (int o = 16; o > 0; o >>= 1)
        se += __shfl_xor_sync(0xffffffffu, se, o);
    float denom = se + expf(snk - mx);
    float rdenom = 1.f / denom;
#pragma unroll
    for (int i = 0; i < 5; i++) {
        int j = lane + i * 32;
        if (j < NKEY) sW[warp * 132 + j] = lgv[i] * rdenom;
    }
    __syncthreads();

    for (int i = tid; i < NKEY * Dh; i += 256) {
        int j = i >> 6, d = i & 63;
        int kj = k0 + j;
        float v;
        if (kj < TC)
            v = cache_v[(((size_t)b * TC + kj) * HKV + hkv) * Dh + d];
        else
            v = vnew[(((size_t)b * Tq + (kj - TC)) * HKV + hkv) * Dh + d];
        sKV[j * 65 + d] = v;
    }
    __syncthreads();

    float a0 = 0.f, a1 = 0.f;
#pragma unroll 4
    for (int j = 0; j < NKEY; j++) {
        float w = sW[warp * 132 + j];
        a0 = fmaf(w, sKV[j * 65 + lane], a0);
        a1 = fmaf(w, sKV[j * 65 + 32 + lane], a1);
    }
    size_t ob = (size_t)row * HID + (hkv * QMULT + warp) * Dh;
    attn[ob + lane] = a0;
    attn[ob + 32 + lane] = a1;
}

// ---------------- launch ----------------
extern "C" void kernel_launch(void* const* d_in, const int* in_sizes, int n_in,
                              void* d_out, int out_size)
{
    int sh = 0;
    if (n_in >= 10) sh = 1;
    else if (n_in == 9 && in_sizes[3] == 1) sh = 1;

    const float* x       = (const float*)d_in[0];
    const float* cache_k = (const float*)d_in[1];
    const float* cache_v = (const float*)d_in[2];
    const float* sinks   = (const float*)d_in[3 + sh];
    const float* norm_w  = (const float*)d_in[4 + sh];
    const float* qkv_w   = (const float*)d_in[5 + sh];
    const float* qkv_b   = (const float*)d_in[6 + sh];
    const float* out_w   = (const float*)d_in[7 + sh];
    const float* out_b   = (const float*)d_in[8 + sh];

    float* out  = (float*)d_out;
    float* Kout = out + OUT_ELEMS;
    float* Vout = Kout + KV_ELEMS;

    float *hp, *qkvp, *attnp, *partp, *knp, *vnp;
    cudaGetSymbolAddress((void**)&hp, g_h);
    cudaGetSymbolAddress((void**)&qkvp, g_qkv);
    cudaGetSymbolAddress((void**)&attnp, g_attn);
    cudaGetSymbolAddress((void**)&partp, g_part);
    cudaGetSymbolAddress((void**)&knp, g_knew);
    cudaGetSymbolAddress((void**)&vnp, g_vnew);

    static cudaStream_t s_copy = nullptr;
    static cudaEvent_t ev_fork = nullptr, ev_join = nullptr;
    static int inited = 0;
    if (!inited) {
        cudaStreamCreateWithFlags(&s_copy, cudaStreamNonBlocking);
        cudaEventCreateWithFlags(&ev_fork, cudaEventDisableTiming);
        cudaEventCreateWithFlags(&ev_join, cudaEventDisableTiming);
        cudaFuncSetAttribute(gemm_tf32_splitk,
                             cudaFuncAttributeMaxDynamicSharedMemorySize,
                             4 * SMTILE * (int)sizeof(float));
        inited = 1;
    }
    const int smem_bytes = 4 * SMTILE * (int)sizeof(float);   // 73728

    // ---- fork: KV cache copy runs concurrently with the whole compute chain
    cudaEventRecord(ev_fork, 0);
    cudaStreamWaitEvent(s_copy, ev_fork, 0);
    copy_kv_kernel<<<4096, 256, 0, s_copy>>>(
        (const float4*)cache_k, (const float4*)cache_v,
        (float4*)Kout, (float4*)Vout);
    cudaEventRecord(ev_join, s_copy);

    // ---- compute chain (default stream)
    rmsnorm_kernel<<<NROW, 256>>>(x, norm_w, hp);
    {
        dim3 grid(QKVD / 128, 3);
        gemm_tf32_splitk<<<grid, 256, smem_bytes>>>(hp, qkv_w, partp, QKVD, HID);
    }
    reduce_qkv_rope<<<NROW, 256>>>(partp, qkv_b, qkvp, Kout, Vout, knp, vnp);
    {
        dim3 grid(HKV, Tq, Bq);
        attn_kernel<<<grid, 256>>>(qkvp, cache_k, cache_v, knp, vnp, sinks, attnp);
    }
    {
        dim3 grid(HID / 128, 4);
        gemm_tf32_splitk<<<grid, 256, smem_bytes>>>(attnp, out_w, partp, HID, HID);
    }
    reduce_out_kernel<<<NROW * HID / 4 / 256, 256>>>(partp, out_b, x, out);

    // ---- join
    cudaStreamWaitEvent(0, ev_join, 0);
}

// round 7
// speedup vs baseline: 3.5643x; 1.0586x over previous
#include <cuda_runtime.h>
#include <cuda_bf16.h>
#include <cuda_fp16.h>
#include <cstdint>
#include <math.h>

// ---------------- problem constants ----------------
#define Bq    8
#define Tq    16
#define HID   4096
#define HQ    64
#define HKV   8
#define Dh    64
#define QMULT 8
#define TC    4096
#define TTOT  (TC + Tq)    // 4112
#define WIN   128
#define NKEY  (WIN + 1)    // 129
#define QKVD  5120
#define NROW  (Bq * Tq)    // 128
#define SM_SCALE 0.125f

#define OUT_ELEMS   ((size_t)NROW * HID)
#define KV_ELEMS    ((size_t)Bq * TTOT * HKV * Dh)

// ---------------- scratch ----------------
__device__ float g_h[NROW * HID];
__device__ float g_qkv[NROW * QKVD];
__device__ float g_attn[NROW * HID];
__device__ float g_part[4 * NROW * QKVD];   // split-K partials (up to S=4)
__device__ float g_knew[NROW * HKV * Dh];
__device__ float g_vnew[NROW * HKV * Dh];

// ---------------- KV cache copy ----------------
__global__ __launch_bounds__(256) void copy_kv_kernel(
    const float4* __restrict__ ck, const float4* __restrict__ cv,
    float4* __restrict__ Kout, float4* __restrict__ Vout)
{
    const int perb = TC * HKV * Dh / 4;
    const int dstb = TTOT * HKV * Dh / 4;
    const int total = Bq * perb;
    for (int i = blockIdx.x * blockDim.x + threadIdx.x; i < total;
         i += gridDim.x * blockDim.x) {
        int b = i / perb;
        int r = i - b * perb;
        int dst = b * dstb + r;
        Kout[dst] = ck[i];
        Vout[dst] = cv[i];
    }
}

// ---------------- rmsnorm ----------------
__global__ __launch_bounds__(256) void rmsnorm_kernel(
    const float* __restrict__ x, const float* __restrict__ w, float* __restrict__ h)
{
    int row = blockIdx.x;
    const float* xr = x + (size_t)row * HID;
    float* hr = h + (size_t)row * HID;
    float ss = 0.f;
    for (int i = threadIdx.x; i < HID; i += 256) {
        float v = xr[i];
        ss += v * v;
    }
    __shared__ float red[256];
    red[threadIdx.x] = ss;
    __syncthreads();
    for (int s = 128; s > 0; s >>= 1) {
        if (threadIdx.x < s) red[threadIdx.x] += red[threadIdx.x + s];
        __syncthreads();
    }
    float inv = rsqrtf(red[0] / (float)HID + 1e-5f);
    for (int i = threadIdx.x; i < HID; i += 256)
        hr[i] = xr[i] * inv * w[i];
}

// ---------------- fp16 mma helpers ----------------
__device__ __forceinline__ uint32_t pack_h2(float x, float y) {
    __half2 h = __floats2half2_rn(x, y);
    return *reinterpret_cast<uint32_t*>(&h);
}

#define LDSM_X4(R0, R1, R2, R3, ADDR)                                       \
    asm volatile(                                                           \
        "ldmatrix.sync.aligned.m8n8.x4.shared.b16 {%0,%1,%2,%3}, [%4];"     \
        : "=r"(R0), "=r"(R1), "=r"(R2), "=r"(R3) : "r"(ADDR))

__device__ __forceinline__ void mma_f16(float c[4], const uint32_t a[4],
                                        const uint32_t b[2]) {
    asm volatile(
        "mma.sync.aligned.m16n8k16.row.col.f32.f16.f16.f32 "
        "{%0,%1,%2,%3}, {%4,%5,%6,%7}, {%8,%9}, {%0,%1,%2,%3};\n"
        : "+f"(c[0]), "+f"(c[1]), "+f"(c[2]), "+f"(c[3])
        : "r"(a[0]), "r"(a[1]), "r"(a[2]), "r"(a[3]), "r"(b[0]), "r"(b[1]));
}

__device__ __forceinline__ uint32_t s2u(const void* p) {
    uint32_t r;
    asm("{ .reg .u64 t; cvta.to.shared.u64 t, %1; cvt.u32.u64 %0, t; }"
        : "=r"(r) : "l"(p));
    return r;
}

// ---------------- fp16 split-K GEMM ----------------
// P_partial[split] = A[128,K]*W[N,K]^T (f32 in, f16 mma, f32 accum).
// BM=128, BN=128, BK=64. 256 threads = 8 warps (4m x 2n), warp tile 32x64.
// grid = (N/128, S).
#define ROWB     144                      // 72 f16 per row (64 + 8 pad)
#define ATILE_B  (128 * ROWB)             // 18432 B
#define STAGE_BB (2 * ATILE_B)            // A + B per stage

__global__ __launch_bounds__(256) void gemm_f16_splitk(
    const float* __restrict__ A, const float* __restrict__ W,
    float* __restrict__ P, int N, int K)
{
    extern __shared__ char dsm[];
    uint32_t sbase = s2u(dsm);

    const int tid = threadIdx.x;
    const int wid = tid >> 5, lane = tid & 31;
    const int wm = (wid >> 1) * 32;
    const int wn = (wid & 1) * 64;
    const int bn = blockIdx.x * 128;

    const int kb = K >> 6;                       // BK=64 tiles
    const int S = gridDim.y;
    const int per = (kb + S - 1) / S;
    const int it0 = blockIdx.y * per;
    const int it1 = min(it0 + per, kb);
    const int nt = it1 - it0;

    const int lrow = tid >> 4;                   // 0..15 (+16 per pass)
    const int c4 = tid & 15;                     // float4 column

    float acc[2][8][4];
#pragma unroll
    for (int mi = 0; mi < 2; mi++)
#pragma unroll
        for (int ni = 0; ni < 8; ni++)
#pragma unroll
            for (int r = 0; r < 4; r++) acc[mi][ni][r] = 0.f;

    uint2 ra[8], rw[8];

#define LDTILE(IT)                                                          \
    {                                                                       \
        int k0 = ((IT) << 6) + c4 * 4;                                      \
        _Pragma("unroll") for (int p = 0; p < 8; p++) {                     \
            int row = lrow + p * 16;                                        \
            float4 av = *(const float4*)(A + (size_t)row * K + k0);         \
            float4 wv = *(const float4*)(W + (size_t)(bn + row) * K + k0);  \
            ra[p] = make_uint2(pack_h2(av.x, av.y), pack_h2(av.z, av.w));   \
            rw[p] = make_uint2(pack_h2(wv.x, wv.y), pack_h2(wv.z, wv.w));   \
        }                                                                   \
    }

#define STTILE(BUF)                                                         \
    {                                                                       \
        uint32_t Abb = sbase + (BUF) * STAGE_BB;                            \
        uint32_t Bbb = Abb + ATILE_B;                                       \
        _Pragma("unroll") for (int p = 0; p < 8; p++) {                     \
            int row = lrow + p * 16;                                        \
            uint32_t off = row * ROWB + c4 * 8;                             \
            asm volatile("st.shared.v2.b32 [%0], {%1,%2};"                  \
                         :: "r"(Abb + off), "r"(ra[p].x), "r"(ra[p].y)      \
                         : "memory");                                       \
            asm volatile("st.shared.v2.b32 [%0], {%1,%2};"                  \
                         :: "r"(Bbb + off), "r"(rw[p].x), "r"(rw[p].y)      \
                         : "memory");                                       \
        }                                                                   \
    }

    LDTILE(it0);
    STTILE(0);
    __syncthreads();

    // ldmatrix lane addressing
    const int a_m = (lane & 7) + (lane & 8);          // row within m16
    const int a_koff = (lane >> 4) * 16;              // k half (bytes)
    const int b_n = (lane & 7) + ((lane >> 4) & 1) * 8;
    const int b_koff = ((lane >> 3) & 1) * 16;

    int buf = 0;
    for (int it = 0; it < nt; ++it) {
        bool more = (it + 1 < nt);
        if (more) LDTILE(it0 + it + 1);

        uint32_t Ab = sbase + buf * STAGE_BB;
        uint32_t Bb = Ab + ATILE_B;
#pragma unroll
        for (int ks = 0; ks < 4; ks++) {
            int kbyte = ks * 32;                       // 16 f16 = 32 B
            uint32_t af[2][4];
#pragma unroll
            for (int mi = 0; mi < 2; mi++) {
                uint32_t addr = Ab + (wm + mi * 16 + a_m) * ROWB + kbyte + a_koff;
                LDSM_X4(af[mi][0], af[mi][1], af[mi][2], af[mi][3], addr);
            }
            uint32_t bf[8][2];
#pragma unroll
            for (int nj = 0; nj < 4; nj++) {
                uint32_t addr = Bb + (wn + nj * 16 + b_n) * ROWB + kbyte + b_koff;
                LDSM_X4(bf[2 * nj][0], bf[2 * nj][1],
                        bf[2 * nj + 1][0], bf[2 * nj + 1][1], addr);
            }
#pragma unroll
            for (int mi = 0; mi < 2; mi++)
#pragma unroll
                for (int ni = 0; ni < 8; ni++)
                    mma_f16(acc[mi][ni], af[mi], bf[ni]);
        }
        if (more) STTILE(buf ^ 1);
        __syncthreads();
        buf ^= 1;
    }

    // epilogue: write partials
    const int g = lane >> 2, t = lane & 3;
    float* Pb = P + (size_t)blockIdx.y * NROW * N;
#pragma unroll
    for (int mi = 0; mi < 2; mi++) {
        int r0 = wm + mi * 16 + g;
#pragma unroll
        for (int ni = 0; ni < 8; ni++) {
            int c = bn + wn + ni * 8 + 2 * t;
            *(float2*)(Pb + (size_t)r0 * N + c) =
                make_float2(acc[mi][ni][0], acc[mi][ni][1]);
            *(float2*)(Pb + (size_t)(r0 + 8) * N + c) =
                make_float2(acc[mi][ni][2], acc[mi][ni][3]);
        }
    }
}

// ---------------- fused QKV reduce(+bias, S=3) + RoPE + K/V scatter ----------------
__global__ __launch_bounds__(256) void reduce_qkv_rope(
    const float* __restrict__ P, const float* __restrict__ bias,
    float* __restrict__ qkv, float* __restrict__ Kout, float* __restrict__ Vout,
    float* __restrict__ knew, float* __restrict__ vnew)
{
    __shared__ float srow[QKVD];
    int row = blockIdx.x;
    int b = row >> 4, t = row & 15, pos = TC + t;
    const int RV4 = QKVD / 4;
    const size_t SPLIT = (size_t)NROW * RV4;
    const float4* P4 = (const float4*)P;
    const float4* B4 = (const float4*)bias;

#pragma unroll
    for (int k = 0; k < 5; k++) {
        int i = threadIdx.x + k * 256;
        size_t off = (size_t)row * RV4 + i;
        float4 a = P4[off];
        float4 p1 = P4[off + SPLIT];
        float4 p2 = P4[off + 2 * SPLIT];
        float4 bb = B4[i];
        a.x += p1.x + p2.x + bb.x;
        a.y += p1.y + p2.y + bb.y;
        a.z += p1.z + p2.z + bb.z;
        a.w += p1.w + p2.w + bb.w;
        *(float4*)&srow[i * 4] = a;
    }
    __syncthreads();

    const float NEG_L2T_32 = -0.537331431f;
    for (int p = threadIdx.x; p < 2048 + 256; p += 256) {
        bool isq = (p < 2048);
        int pp = isq ? p : p - 2048;
        int head = pp >> 5, j = pp & 31;
        int base = (isq ? head * 64 : HQ * Dh + head * 64);
        float invf = exp2f((float)j * NEG_L2T_32);
        float ang = (float)pos * invf;
        float c = cosf(ang), s = sinf(ang);
        float x1 = srow[base + j], x2 = srow[base + j + 32];
        float r1 = x1 * c - x2 * s;
        float r2 = x2 * c + x1 * s;
        if (isq) {
            qkv[(size_t)row * QKVD + base + j] = r1;
            qkv[(size_t)row * QKVD + base + j + 32] = r2;
        } else {
            size_t o = ((((size_t)b * TTOT) + pos) * HKV + head) * Dh;
            Kout[o + j] = r1;
            Kout[o + j + 32] = r2;
            size_t on = (((size_t)row * HKV) + head) * Dh;
            knew[on + j] = r1;
            knew[on + j + 32] = r2;
        }
    }
    for (int i = threadIdx.x; i < HKV * Dh; i += 256) {
        float v = srow[(HQ + HKV) * Dh + i];
        Vout[(((size_t)b * TTOT) + pos) * HKV * Dh + i] = v;
        vnew[(size_t)row * HKV * Dh + i] = v;
    }
}

// ---------------- OUT reduce: 4 splits + bias + residual ----------------
__global__ __launch_bounds__(256) void reduce_out_kernel(
    const float* __restrict__ P, const float* __restrict__ bias,
    const float* __restrict__ x, float* __restrict__ out)
{
    int i = blockIdx.x * 256 + threadIdx.x;
    const int TOT = NROW * HID / 4;
    const float4* P4 = (const float4*)P;
    float4 a = P4[i];
    float4 p1 = P4[i + TOT];
    float4 p2 = P4[i + 2 * TOT];
    float4 p3 = P4[i + 3 * TOT];
    float4 bb = ((const float4*)bias)[i & (HID / 4 - 1)];
    float4 rr = ((const float4*)x)[i];
    a.x += p1.x + p2.x + p3.x + bb.x + rr.x;
    a.y += p1.y + p2.y + p3.y + bb.y + rr.y;
    a.z += p1.z + p2.z + p3.z + bb.z + rr.z;
    a.w += p1.w + p2.w + p3.w + bb.w + rr.w;
    ((float4*)out)[i] = a;
}

// ---------------- windowed attention with sink ----------------
__global__ __launch_bounds__(256) void attn_kernel(
    const float* __restrict__ qkv,
    const float* __restrict__ cache_k, const float* __restrict__ cache_v,
    const float* __restrict__ knew, const float* __restrict__ vnew,
    const float* __restrict__ sinks, float* __restrict__ attn)
{
    int hkv = blockIdx.x;
    int t = blockIdx.y;
    int b = blockIdx.z;
    int row = b * Tq + t;
    int k0 = TC + t - WIN;

    __shared__ float sKV[NKEY * 65];
    __shared__ float sQ[QMULT * Dh];
    __shared__ float sW[QMULT * 132];

    int tid = threadIdx.x;
    int warp = tid >> 5, lane = tid & 31;

    for (int i = tid; i < QMULT * Dh; i += 256)
        sQ[i] = qkv[(size_t)row * QKVD + hkv * (QMULT * Dh) + i];

    for (int i = tid; i < NKEY * Dh; i += 256) {
        int j = i >> 6, d = i & 63;
        int kj = k0 + j;
        float v;
        if (kj < TC)
            v = cache_k[(((size_t)b * TC + kj) * HKV + hkv) * Dh + d];
        else
            v = knew[(((size_t)b * Tq + (kj - TC)) * HKV + hkv) * Dh + d];
        sKV[j * 65 + d] = v;
    }
    __syncthreads();

    float lgv[5];
    float mx = -INFINITY;
#pragma unroll
    for (int i = 0; i < 5; i++) {
        int j = lane + i * 32;
        float acc = -INFINITY;
        if (j < NKEY) {
            acc = 0.f;
            const float* qq = &sQ[warp * Dh];
            const float* kk = &sKV[j * 65];
#pragma unroll 8
            for (int d = 0; d < Dh; d++) acc = fmaf(qq[d], kk[d], acc);
            acc *= SM_SCALE;
        }
        lgv[i] = acc;
        mx = fmaxf(mx, acc);
    }
#pragma unroll
    for (int o = 16; o > 0; o >>= 1)
        mx = fmaxf(mx, __shfl_xor_sync(0xffffffffu, mx, o));
    float snk = sinks[hkv * QMULT + warp];
    mx = fmaxf(mx, snk);

    float se = 0.f;
#pragma unroll
    for (int i = 0; i < 5; i++) {
        int j = lane + i * 32;
        if (j < NKEY) {
            lgv[i] = expf(lgv[i] - mx);
            se += lgv[i];
        }
    }
#pragma unroll
    for (int o = 16; o > 0; o >>= 1)
        se += __shfl_xor_sync(0xffffffffu, se, o);
    float denom = se + expf(snk - mx);
    float rdenom = 1.f / denom;
#pragma unroll
    for (int i = 0; i < 5; i++) {
        int j = lane + i * 32;
        if (j < NKEY) sW[warp * 132 + j] = lgv[i] * rdenom;
    }
    __syncthreads();

    for (int i = tid; i < NKEY * Dh; i += 256) {
        int j = i >> 6, d = i & 63;
        int kj = k0 + j;
        float v;
        if (kj < TC)
            v = cache_v[(((size_t)b * TC + kj) * HKV + hkv) * Dh + d];
        else
            v = vnew[(((size_t)b * Tq + (kj - TC)) * HKV + hkv) * Dh + d];
        sKV[j * 65 + d] = v;
    }
    __syncthreads();

    float a0 = 0.f, a1 = 0.f;
#pragma unroll 4
    for (int j = 0; j < NKEY; j++) {
        float w = sW[warp * 132 + j];
        a0 = fmaf(w, sKV[j * 65 + lane], a0);
        a1 = fmaf(w, sKV[j * 65 + 32 + lane], a1);
    }
    size_t ob = (size_t)row * HID + (hkv * QMULT + warp) * Dh;
    attn[ob + lane] = a0;
    attn[ob + 32 + lane] = a1;
}

// ---------------- launch ----------------
extern "C" void kernel_launch(void* const* d_in, const int* in_sizes, int n_in,
                              void* d_out, int out_size)
{
    int sh = 0;
    if (n_in >= 10) sh = 1;
    else if (n_in == 9 && in_sizes[3] == 1) sh = 1;

    const float* x       = (const float*)d_in[0];
    const float* cache_k = (const float*)d_in[1];
    const float* cache_v = (const float*)d_in[2];
    const float* sinks   = (const float*)d_in[3 + sh];
    const float* norm_w  = (const float*)d_in[4 + sh];
    const float* qkv_w   = (const float*)d_in[5 + sh];
    const float* qkv_b   = (const float*)d_in[6 + sh];
    const float* out_w   = (const float*)d_in[7 + sh];
    const float* out_b   = (const float*)d_in[8 + sh];

    float* out  = (float*)d_out;
    float* Kout = out + OUT_ELEMS;
    float* Vout = Kout + KV_ELEMS;

    float *hp, *qkvp, *attnp, *partp, *knp, *vnp;
    cudaGetSymbolAddress((void**)&hp, g_h);
    cudaGetSymbolAddress((void**)&qkvp, g_qkv);
    cudaGetSymbolAddress((void**)&attnp, g_attn);
    cudaGetSymbolAddress((void**)&partp, g_part);
    cudaGetSymbolAddress((void**)&knp, g_knew);
    cudaGetSymbolAddress((void**)&vnp, g_vnew);

    static cudaStream_t s_copy = nullptr;
    static cudaEvent_t ev_fork = nullptr, ev_join = nullptr;
    static int inited = 0;
    if (!inited) {
        cudaStreamCreateWithFlags(&s_copy, cudaStreamNonBlocking);
        cudaEventCreateWithFlags(&ev_fork, cudaEventDisableTiming);
        cudaEventCreateWithFlags(&ev_join, cudaEventDisableTiming);
        cudaFuncSetAttribute(gemm_f16_splitk,
                             cudaFuncAttributeMaxDynamicSharedMemorySize,
                             2 * STAGE_BB);
        inited = 1;
    }
    const int smem_bytes = 2 * STAGE_BB;   // 73728

    // fork: KV cache copy overlaps the compute chain
    cudaEventRecord(ev_fork, 0);
    cudaStreamWaitEvent(s_copy, ev_fork, 0);
    copy_kv_kernel<<<4096, 256, 0, s_copy>>>(
        (const float4*)cache_k, (const float4*)cache_v,
        (float4*)Kout, (float4*)Vout);
    cudaEventRecord(ev_join, s_copy);

    // compute chain
    rmsnorm_kernel<<<NROW, 256>>>(x, norm_w, hp);
    {
        dim3 grid(QKVD / 128, 3);
        gemm_f16_splitk<<<grid, 256, smem_bytes>>>(hp, qkv_w, partp, QKVD, HID);
    }
    reduce_qkv_rope<<<NROW, 256>>>(partp, qkv_b, qkvp, Kout, Vout, knp, vnp);
    {
        dim3 grid(HKV, Tq, Bq);
        attn_kernel<<<grid, 256>>>(qkvp, cache_k, cache_v, knp, vnp, sinks, attnp);
    }
    {
        dim3 grid(HID / 128, 4);
        gemm_f16_splitk<<<grid, 256, smem_bytes>>>(attnp, out_w, partp, HID, HID);
    }
    reduce_out_kernel<<<NROW * HID / 4 / 256, 256>>>(partp, out_b, x, out);

    cudaStreamWaitEvent(0, ev_join, 0);
}

// round 8
// speedup vs baseline: 3.9086x; 1.0966x over previous
#include <cuda_runtime.h>
#include <cuda_bf16.h>
#include <cuda_fp16.h>
#include <cstdint>
#include <math.h>

// ---------------- problem constants ----------------
#define Bq    8
#define Tq    16
#define HID   4096
#define HQ    64
#define HKV   8
#define Dh    64
#define QMULT 8
#define TC    4096
#define TTOT  (TC + Tq)    // 4112
#define WIN   128
#define NKEY  (WIN + 1)    // 129
#define QKVD  5120
#define NROW  (Bq * Tq)    // 128
#define SM_SCALE 0.125f

#define OUT_ELEMS   ((size_t)NROW * HID)
#define KV_ELEMS    ((size_t)Bq * TTOT * HKV * Dh)

// ---------------- scratch ----------------
__device__ float g_h[NROW * HID];
__device__ float g_qkv[NROW * QKVD];
__device__ float g_attn[NROW * HID];
__device__ float g_part[4 * NROW * QKVD];
__device__ float g_knew[NROW * HKV * Dh];
__device__ float g_vnew[NROW * HKV * Dh];

// ---------------- KV cache copy: one tensor, 128 CTAs, static loop ----------------
// perb = TC*HKV*Dh/4 = 524288 = 2^19 vec4 per batch
#define PERB_SHIFT 19
#define CPY_CTAS   128
#define CPY_THREADS 256
#define CPY_TOTAL  (Bq << PERB_SHIFT)                 // 4194304 vec4
#define CPY_ITERS  (CPY_TOTAL / (CPY_CTAS * CPY_THREADS))   // 128

__global__ __launch_bounds__(CPY_THREADS) void copy_one_kernel(
    const float4* __restrict__ src, float4* __restrict__ dst)
{
    const int dstb = TTOT * HKV * Dh / 4;             // 526336
    int base = blockIdx.x * CPY_THREADS + threadIdx.x;
    const int NT = CPY_CTAS * CPY_THREADS;            // 32768
#pragma unroll 8
    for (int j = 0; j < CPY_ITERS; j++) {
        int i = base + j * NT;
        int b = i >> PERB_SHIFT;
        int r = i & ((1 << PERB_SHIFT) - 1);
        dst[b * dstb + r] = src[i];
    }
}

// ---------------- rmsnorm ----------------
__global__ __launch_bounds__(256) void rmsnorm_kernel(
    const float* __restrict__ x, const float* __restrict__ w, float* __restrict__ h)
{
    int row = blockIdx.x;
    const float* xr = x + (size_t)row * HID;
    float* hr = h + (size_t)row * HID;
    float ss = 0.f;
    for (int i = threadIdx.x; i < HID; i += 256) {
        float v = xr[i];
        ss += v * v;
    }
    __shared__ float red[256];
    red[threadIdx.x] = ss;
    __syncthreads();
    for (int s = 128; s > 0; s >>= 1) {
        if (threadIdx.x < s) red[threadIdx.x] += red[threadIdx.x + s];
        __syncthreads();
    }
    float inv = rsqrtf(red[0] / (float)HID + 1e-5f);
    for (int i = threadIdx.x; i < HID; i += 256)
        hr[i] = xr[i] * inv * w[i];
}

// ---------------- fp16 mma helpers ----------------
__device__ __forceinline__ uint32_t pack_h2(float x, float y) {
    __half2 h = __floats2half2_rn(x, y);
    return *reinterpret_cast<uint32_t*>(&h);
}

#define LDSM_X4(R0, R1, R2, R3, ADDR)                                       \
    asm volatile(                                                           \
        "ldmatrix.sync.aligned.m8n8.x4.shared.b16 {%0,%1,%2,%3}, [%4];"     \
        : "=r"(R0), "=r"(R1), "=r"(R2), "=r"(R3) : "r"(ADDR))

__device__ __forceinline__ void mma_f16(float c[4], const uint32_t a[4],
                                        const uint32_t b[2]) {
    asm volatile(
        "mma.sync.aligned.m16n8k16.row.col.f32.f16.f16.f32 "
        "{%0,%1,%2,%3}, {%4,%5,%6,%7}, {%8,%9}, {%0,%1,%2,%3};\n"
        : "+f"(c[0]), "+f"(c[1]), "+f"(c[2]), "+f"(c[3])
        : "r"(a[0]), "r"(a[1]), "r"(a[2]), "r"(a[3]), "r"(b[0]), "r"(b[1]));
}

__device__ __forceinline__ uint32_t s2u(const void* p) {
    uint32_t r;
    asm("{ .reg .u64 t; cvta.to.shared.u64 t, %1; cvt.u32.u64 %0, t; }"
        : "=r"(r) : "l"(p));
    return r;
}

// ---------------- fp16 split-K GEMM ----------------
#define ROWB     144
#define ATILE_B  (128 * ROWB)
#define STAGE_BB (2 * ATILE_B)

__global__ __launch_bounds__(256) void gemm_f16_splitk(
    const float* __restrict__ A, const float* __restrict__ W,
    float* __restrict__ P, int N, int K)
{
    extern __shared__ char dsm[];
    uint32_t sbase = s2u(dsm);

    const int tid = threadIdx.x;
    const int wid = tid >> 5, lane = tid & 31;
    const int wm = (wid >> 1) * 32;
    const int wn = (wid & 1) * 64;
    const int bn = blockIdx.x * 128;

    const int kb = K >> 6;
    const int S = gridDim.y;
    const int per = (kb + S - 1) / S;
    const int it0 = blockIdx.y * per;
    const int it1 = min(it0 + per, kb);
    const int nt = it1 - it0;

    const int lrow = tid >> 4;
    const int c4 = tid & 15;

    float acc[2][8][4];
#pragma unroll
    for (int mi = 0; mi < 2; mi++)
#pragma unroll
        for (int ni = 0; ni < 8; ni++)
#pragma unroll
            for (int r = 0; r < 4; r++) acc[mi][ni][r] = 0.f;

    uint2 ra[8], rw[8];

#define LDTILE(IT)                                                          \
    {                                                                       \
        int k0 = ((IT) << 6) + c4 * 4;                                      \
        _Pragma("unroll") for (int p = 0; p < 8; p++) {                     \
            int row = lrow + p * 16;                                        \
            float4 av = *(const float4*)(A + (size_t)row * K + k0);         \
            float4 wv = *(const float4*)(W + (size_t)(bn + row) * K + k0);  \
            ra[p] = make_uint2(pack_h2(av.x, av.y), pack_h2(av.z, av.w));   \
            rw[p] = make_uint2(pack_h2(wv.x, wv.y), pack_h2(wv.z, wv.w));   \
        }                                                                   \
    }

#define STTILE(BUF)                                                         \
    {                                                                       \
        uint32_t Abb = sbase + (BUF) * STAGE_BB;                            \
        uint32_t Bbb = Abb + ATILE_B;                                       \
        _Pragma("unroll") for (int p = 0; p < 8; p++) {                     \
            int row = lrow + p * 16;                                        \
            uint32_t off = row * ROWB + c4 * 8;                             \
            asm volatile("st.shared.v2.b32 [%0], {%1,%2};"                  \
                         :: "r"(Abb + off), "r"(ra[p].x), "r"(ra[p].y)      \
                         : "memory");                                       \
            asm volatile("st.shared.v2.b32 [%0], {%1,%2};"                  \
                         :: "r"(Bbb + off), "r"(rw[p].x), "r"(rw[p].y)      \
                         : "memory");                                       \
        }                                                                   \
    }

    LDTILE(it0);
    STTILE(0);
    __syncthreads();

    const int a_m = (lane & 7) + (lane & 8);
    const int a_koff = (lane >> 4) * 16;
    const int b_n = (lane & 7) + ((lane >> 4) & 1) * 8;
    const int b_koff = ((lane >> 3) & 1) * 16;

    int buf = 0;
    for (int it = 0; it < nt; ++it) {
        bool more = (it + 1 < nt);
        if (more) LDTILE(it0 + it + 1);

        uint32_t Ab = sbase + buf * STAGE_BB;
        uint32_t Bb = Ab + ATILE_B;
#pragma unroll
        for (int ks = 0; ks < 4; ks++) {
            int kbyte = ks * 32;
            uint32_t af[2][4];
#pragma unroll
            for (int mi = 0; mi < 2; mi++) {
                uint32_t addr = Ab + (wm + mi * 16 + a_m) * ROWB + kbyte + a_koff;
                LDSM_X4(af[mi][0], af[mi][1], af[mi][2], af[mi][3], addr);
            }
            uint32_t bf[8][2];
#pragma unroll
            for (int nj = 0; nj < 4; nj++) {
                uint32_t addr = Bb + (wn + nj * 16 + b_n) * ROWB + kbyte + b_koff;
                LDSM_X4(bf[2 * nj][0], bf[2 * nj][1],
                        bf[2 * nj + 1][0], bf[2 * nj + 1][1], addr);
            }
#pragma unroll
            for (int mi = 0; mi < 2; mi++)
#pragma unroll
                for (int ni = 0; ni < 8; ni++)
                    mma_f16(acc[mi][ni], af[mi], bf[ni]);
        }
        if (more) STTILE(buf ^ 1);
        __syncthreads();
        buf ^= 1;
    }

    const int g = lane >> 2, t = lane & 3;
    float* Pb = P + (size_t)blockIdx.y * NROW * N;
#pragma unroll
    for (int mi = 0; mi < 2; mi++) {
        int r0 = wm + mi * 16 + g;
#pragma unroll
        for (int ni = 0; ni < 8; ni++) {
            int c = bn + wn + ni * 8 + 2 * t;
            *(float2*)(Pb + (size_t)r0 * N + c) =
                make_float2(acc[mi][ni][0], acc[mi][ni][1]);
            *(float2*)(Pb + (size_t)(r0 + 8) * N + c) =
                make_float2(acc[mi][ni][2], acc[mi][ni][3]);
        }
    }
}

// ---------------- fused QKV reduce(+bias, S=3) + RoPE + K/V scatter ----------------
__global__ __launch_bounds__(256) void reduce_qkv_rope(
    const float* __restrict__ P, const float* __restrict__ bias,
    float* __restrict__ qkv, float* __restrict__ Kout, float* __restrict__ Vout,
    float* __restrict__ knew, float* __restrict__ vnew)
{
    __shared__ float srow[QKVD];
    int row = blockIdx.x;
    int b = row >> 4, t = row & 15, pos = TC + t;
    const int RV4 = QKVD / 4;
    const size_t SPLIT = (size_t)NROW * RV4;
    const float4* P4 = (const float4*)P;
    const float4* B4 = (const float4*)bias;

#pragma unroll
    for (int k = 0; k < 5; k++) {
        int i = threadIdx.x + k * 256;
        size_t off = (size_t)row * RV4 + i;
        float4 a = P4[off];
        float4 p1 = P4[off + SPLIT];
        float4 p2 = P4[off + 2 * SPLIT];
        float4 bb = B4[i];
        a.x += p1.x + p2.x + bb.x;
        a.y += p1.y + p2.y + bb.y;
        a.z += p1.z + p2.z + bb.z;
        a.w += p1.w + p2.w + bb.w;
        *(float4*)&srow[i * 4] = a;
    }
    __syncthreads();

    const float NEG_L2T_32 = -0.537331431f;
    for (int p = threadIdx.x; p < 2048 + 256; p += 256) {
        bool isq = (p < 2048);
        int pp = isq ? p : p - 2048;
        int head = pp >> 5, j = pp & 31;
        int base = (isq ? head * 64 : HQ * Dh + head * 64);
        float invf = exp2f((float)j * NEG_L2T_32);
        float ang = (float)pos * invf;
        float c = cosf(ang), s = sinf(ang);
        float x1 = srow[base + j], x2 = srow[base + j + 32];
        float r1 = x1 * c - x2 * s;
        float r2 = x2 * c + x1 * s;
        if (isq) {
            qkv[(size_t)row * QKVD + base + j] = r1;
            qkv[(size_t)row * QKVD + base + j + 32] = r2;
        } else {
            size_t o = ((((size_t)b * TTOT) + pos) * HKV + head) * Dh;
            Kout[o + j] = r1;
            Kout[o + j + 32] = r2;
            size_t on = (((size_t)row * HKV) + head) * Dh;
            knew[on + j] = r1;
            knew[on + j + 32] = r2;
        }
    }
    for (int i = threadIdx.x; i < HKV * Dh; i += 256) {
        float v = srow[(HQ + HKV) * Dh + i];
        Vout[(((size_t)b * TTOT) + pos) * HKV * Dh + i] = v;
        vnew[(size_t)row * HKV * Dh + i] = v;
    }
}

// ---------------- OUT reduce: 4 splits + bias + residual ----------------
__global__ __launch_bounds__(256) void reduce_out_kernel(
    const float* __restrict__ P, const float* __restrict__ bias,
    const float* __restrict__ x, float* __restrict__ out)
{
    int i = blockIdx.x * 256 + threadIdx.x;
    const int TOT = NROW * HID / 4;
    const float4* P4 = (const float4*)P;
    float4 a = P4[i];
    float4 p1 = P4[i + TOT];
    float4 p2 = P4[i + 2 * TOT];
    float4 p3 = P4[i + 3 * TOT];
    float4 bb = ((const float4*)bias)[i & (HID / 4 - 1)];
    float4 rr = ((const float4*)x)[i];
    a.x += p1.x + p2.x + p3.x + bb.x + rr.x;
    a.y += p1.y + p2.y + p3.y + bb.y + rr.y;
    a.z += p1.z + p2.z + p3.z + bb.z + rr.z;
    a.w += p1.w + p2.w + p3.w + bb.w + rr.w;
    ((float4*)out)[i] = a;
}

// ---------------- windowed attention with sink ----------------
__global__ __launch_bounds__(256) void attn_kernel(
    const float* __restrict__ qkv,
    const float* __restrict__ cache_k, const float* __restrict__ cache_v,
    const float* __restrict__ knew, const float* __restrict__ vnew,
    const float* __restrict__ sinks, float* __restrict__ attn)
{
    int hkv = blockIdx.x;
    int t = blockIdx.y;
    int b = blockIdx.z;
    int row = b * Tq + t;
    int k0 = TC + t - WIN;

    __shared__ float sKV[NKEY * 65];
    __shared__ float sQ[QMULT * Dh];
    __shared__ float sW[QMULT * 132];

    int tid = threadIdx.x;
    int warp = tid >> 5, lane = tid & 31;

    for (int i = tid; i < QMULT * Dh; i += 256)
        sQ[i] = qkv[(size_t)row * QKVD + hkv * (QMULT * Dh) + i];

    for (int i = tid; i < NKEY * Dh; i += 256) {
        int j = i >> 6, d = i & 63;
        int kj = k0 + j;
        float v;
        if (kj < TC)
            v = cache_k[(((size_t)b * TC + kj) * HKV + hkv) * Dh + d];
        else
            v = knew[(((size_t)b * Tq + (kj - TC)) * HKV + hkv) * Dh + d];
        sKV[j * 65 + d] = v;
    }
    __syncthreads();

    float lgv[5];
    float mx = -INFINITY;
#pragma unroll
    for (int i = 0; i < 5; i++) {
        int j = lane + i * 32;
        float acc = -INFINITY;
        if (j < NKEY) {
            acc = 0.f;
            const float* qq = &sQ[warp * Dh];
            const float* kk = &sKV[j * 65];
#pragma unroll 8
            for (int d = 0; d < Dh; d++) acc = fmaf(qq[d], kk[d], acc);
            acc *= SM_SCALE;
        }
        lgv[i] = acc;
        mx = fmaxf(mx, acc);
    }
#pragma unroll
    for (int o = 16; o > 0; o >>= 1)
        mx = fmaxf(mx, __shfl_xor_sync(0xffffffffu, mx, o));
    float snk = sinks[hkv * QMULT + warp];
    mx = fmaxf(mx, snk);

    float se = 0.f;
#pragma unroll
    for (int i = 0; i < 5; i++) {
        int j = lane + i * 32;
        if (j < NKEY) {
            lgv[i] = expf(lgv[i] - mx);
            se += lgv[i];
        }
    }
#pragma unroll
    for (int o = 16; o > 0; o >>= 1)
        se += __shfl_xor_sync(0xffffffffu, se, o);
    float denom = se + expf(snk - mx);
    float rdenom = 1.f / denom;
#pragma unroll
    for (int i = 0; i < 5; i++) {
        int j = lane + i * 32;
        if (j < NKEY) sW[warp * 132 + j] = lgv[i] * rdenom;
    }
    __syncthreads();

    for (int i = tid; i < NKEY * Dh; i += 256) {
        int j = i >> 6, d = i & 63;
        int kj = k0 + j;
        float v;
        if (kj < TC)
            v = cache_v[(((size_t)b * TC + kj) * HKV + hkv) * Dh + d];
        else
            v = vnew[(((size_t)b * Tq + (kj - TC)) * HKV + hkv) * Dh + d];
        sKV[j * 65 + d] = v;
    }
    __syncthreads();

    float a0 = 0.f, a1 = 0.f;
#pragma unroll 4
    for (int j = 0; j < NKEY; j++) {
        float w = sW[warp * 132 + j];
        a0 = fmaf(w, sKV[j * 65 + lane], a0);
        a1 = fmaf(w, sKV[j * 65 + 32 + lane], a1);
    }
    size_t ob = (size_t)row * HID + (hkv * QMULT + warp) * Dh;
    attn[ob + lane] = a0;
    attn[ob + 32 + lane] = a1;
}

// ---------------- launch ----------------
extern "C" void kernel_launch(void* const* d_in, const int* in_sizes, int n_in,
                              void* d_out, int out_size)
{
    int sh = 0;
    if (n_in >= 10) sh = 1;
    else if (n_in == 9 && in_sizes[3] == 1) sh = 1;

    const float* x       = (const float*)d_in[0];
    const float* cache_k = (const float*)d_in[1];
    const float* cache_v = (const float*)d_in[2];
    const float* sinks   = (const float*)d_in[3 + sh];
    const float* norm_w  = (const float*)d_in[4 + sh];
    const float* qkv_w   = (const float*)d_in[5 + sh];
    const float* qkv_b   = (const float*)d_in[6 + sh];
    const float* out_w   = (const float*)d_in[7 + sh];
    const float* out_b   = (const float*)d_in[8 + sh];

    float* out  = (float*)d_out;
    float* Kout = out + OUT_ELEMS;
    float* Vout = Kout + KV_ELEMS;

    float *hp, *qkvp, *attnp, *partp, *knp, *vnp;
    cudaGetSymbolAddress((void**)&hp, g_h);
    cudaGetSymbolAddress((void**)&qkvp, g_qkv);
    cudaGetSymbolAddress((void**)&attnp, g_attn);
    cudaGetSymbolAddress((void**)&partp, g_part);
    cudaGetSymbolAddress((void**)&knp, g_knew);
    cudaGetSymbolAddress((void**)&vnp, g_vnew);

    static cudaStream_t s_copy = nullptr;
    static cudaEvent_t ev_fork = nullptr, ev_join = nullptr;
    static int inited = 0;
    if (!inited) {
        cudaStreamCreateWithFlags(&s_copy, cudaStreamNonBlocking);
        cudaEventCreateWithFlags(&ev_fork, cudaEventDisableTiming);
        cudaEventCreateWithFlags(&ev_join, cudaEventDisableTiming);
        cudaFuncSetAttribute(gemm_f16_splitk,
                             cudaFuncAttributeMaxDynamicSharedMemorySize,
                             2 * STAGE_BB);
        inited = 1;
    }
    const int smem_bytes = 2 * STAGE_BB;   // 73728

    // fork: K and V cache copies on side stream, small grids so they
    // co-reside with the compute chain instead of flooding the SMs.
    cudaEventRecord(ev_fork, 0);
    cudaStreamWaitEvent(s_copy, ev_fork, 0);
    copy_one_kernel<<<CPY_CTAS, CPY_THREADS, 0, s_copy>>>(
        (const float4*)cache_k, (float4*)Kout);
    copy_one_kernel<<<CPY_CTAS, CPY_THREADS, 0, s_copy>>>(
        (const float4*)cache_v, (float4*)Vout);
    cudaEventRecord(ev_join, s_copy);

    // compute chain (gemm_qkv is the 4th launch -> gets profiled by ncu)
    rmsnorm_kernel<<<NROW, 256>>>(x, norm_w, hp);
    {
        dim3 grid(QKVD / 128, 3);
        gemm_f16_splitk<<<grid, 256, smem_bytes>>>(hp, qkv_w, partp, QKVD, HID);
    }
    reduce_qkv_rope<<<NROW, 256>>>(partp, qkv_b, qkvp, Kout, Vout, knp, vnp);
    {
        dim3 grid(HKV, Tq, Bq);
        attn_kernel<<<grid, 256>>>(qkvp, cache_k, cache_v, knp, vnp, sinks, attnp);
    }
    {
        dim3 grid(HID / 128, 4);
        gemm_f16_splitk<<<grid, 256, smem_bytes>>>(attnp, out_w, partp, HID, HID);
    }
    reduce_out_kernel<<<NROW * HID / 4 / 256, 256>>>(partp, out_b, x, out);

    cudaStreamWaitEvent(0, ev_join, 0);
}

// round 9
// speedup vs baseline: 4.4160x; 1.1298x over previous
#include <cuda_runtime.h>
#include <cuda_bf16.h>
#include <cuda_fp16.h>
#include <cstdint>
#include <math.h>

// ---------------- problem constants ----------------
#define Bq    8
#define Tq    16
#define HID   4096
#define HQ    64
#define HKV   8
#define Dh    64
#define QMULT 8
#define TC    4096
#define TTOT  (TC + Tq)    // 4112
#define WIN   128
#define NKEY  (WIN + 1)    // 129
#define QKVD  5120
#define NROW  (Bq * Tq)    // 128
#define SM_SCALE 0.125f

#define S_QKV 6
#define S_OUT 8

#define OUT_ELEMS   ((size_t)NROW * HID)
#define KV_ELEMS    ((size_t)Bq * TTOT * HKV * Dh)

// ---------------- scratch ----------------
__device__ float g_h[NROW * HID];
__device__ float g_qkv[NROW * QKVD];
__device__ float g_attn[NROW * HID];
__device__ float g_part[8 * NROW * QKVD];   // split-K partials (up to S=8)
__device__ float g_knew[NROW * HKV * Dh];
__device__ float g_vnew[NROW * HKV * Dh];

// ---------------- KV cache copy: one tensor, 128 CTAs, static loop ----------------
#define PERB_SHIFT 19
#define CPY_CTAS   128
#define CPY_THREADS 256
#define CPY_TOTAL  (Bq << PERB_SHIFT)
#define CPY_ITERS  (CPY_TOTAL / (CPY_CTAS * CPY_THREADS))   // 128

__global__ __launch_bounds__(CPY_THREADS) void copy_one_kernel(
    const float4* __restrict__ src, float4* __restrict__ dst)
{
    const int dstb = TTOT * HKV * Dh / 4;
    int base = blockIdx.x * CPY_THREADS + threadIdx.x;
    const int NT = CPY_CTAS * CPY_THREADS;
#pragma unroll 8
    for (int j = 0; j < CPY_ITERS; j++) {
        int i = base + j * NT;
        int b = i >> PERB_SHIFT;
        int r = i & ((1 << PERB_SHIFT) - 1);
        dst[b * dstb + r] = src[i];
    }
}

// ---------------- rmsnorm ----------------
__global__ __launch_bounds__(256) void rmsnorm_kernel(
    const float* __restrict__ x, const float* __restrict__ w, float* __restrict__ h)
{
    int row = blockIdx.x;
    const float* xr = x + (size_t)row * HID;
    float* hr = h + (size_t)row * HID;
    float ss = 0.f;
    for (int i = threadIdx.x; i < HID; i += 256) {
        float v = xr[i];
        ss += v * v;
    }
    __shared__ float red[256];
    red[threadIdx.x] = ss;
    __syncthreads();
    for (int s = 128; s > 0; s >>= 1) {
        if (threadIdx.x < s) red[threadIdx.x] += red[threadIdx.x + s];
        __syncthreads();
    }
    float inv = rsqrtf(red[0] / (float)HID + 1e-5f);
    for (int i = threadIdx.x; i < HID; i += 256)
        hr[i] = xr[i] * inv * w[i];
}

// ---------------- fp16 mma helpers ----------------
__device__ __forceinline__ uint32_t pack_h2(float x, float y) {
    __half2 h = __floats2half2_rn(x, y);
    return *reinterpret_cast<uint32_t*>(&h);
}

#define LDSM_X4(R0, R1, R2, R3, ADDR)                                       \
    asm volatile(                                                           \
        "ldmatrix.sync.aligned.m8n8.x4.shared.b16 {%0,%1,%2,%3}, [%4];"     \
        : "=r"(R0), "=r"(R1), "=r"(R2), "=r"(R3) : "r"(ADDR))

__device__ __forceinline__ void mma_f16(float c[4], const uint32_t a[4],
                                        const uint32_t b[2]) {
    asm volatile(
        "mma.sync.aligned.m16n8k16.row.col.f32.f16.f16.f32 "
        "{%0,%1,%2,%3}, {%4,%5,%6,%7}, {%8,%9}, {%0,%1,%2,%3};\n"
        : "+f"(c[0]), "+f"(c[1]), "+f"(c[2]), "+f"(c[3])
        : "r"(a[0]), "r"(a[1]), "r"(a[2]), "r"(a[3]), "r"(b[0]), "r"(b[1]));
}

__device__ __forceinline__ uint32_t s2u(const void* p) {
    uint32_t r;
    asm("{ .reg .u64 t; cvta.to.shared.u64 t, %1; cvt.u32.u64 %0, t; }"
        : "=r"(r) : "l"(p));
    return r;
}

// ---------------- fp16 split-K GEMM (2 CTAs/SM) ----------------
#define ROWB     144
#define ATILE_B  (128 * ROWB)
#define STAGE_BB (2 * ATILE_B)

__global__ __launch_bounds__(256, 2) void gemm_f16_splitk(
    const float* __restrict__ A, const float* __restrict__ W,
    float* __restrict__ P, int N, int K)
{
    extern __shared__ char dsm[];
    uint32_t sbase = s2u(dsm);

    const int tid = threadIdx.x;
    const int wid = tid >> 5, lane = tid & 31;
    const int wm = (wid >> 1) * 32;
    const int wn = (wid & 1) * 64;
    const int bn = blockIdx.x * 128;

    const int kb = K >> 6;
    const int S = gridDim.y;
    const int per = (kb + S - 1) / S;
    const int it0 = blockIdx.y * per;
    const int it1 = min(it0 + per, kb);
    const int nt = it1 - it0;

    const int lrow = tid >> 4;
    const int c4 = tid & 15;

    float acc[2][8][4];
#pragma unroll
    for (int mi = 0; mi < 2; mi++)
#pragma unroll
        for (int ni = 0; ni < 8; ni++)
#pragma unroll
            for (int r = 0; r < 4; r++) acc[mi][ni][r] = 0.f;

    uint2 ra[8], rw[8];

#define LDTILE(IT)                                                          \
    {                                                                       \
        int k0 = ((IT) << 6) + c4 * 4;                                      \
        _Pragma("unroll") for (int p = 0; p < 8; p++) {                     \
            int row = lrow + p * 16;                                        \
            float4 av = *(const float4*)(A + (size_t)row * K + k0);         \
            float4 wv = *(const float4*)(W + (size_t)(bn + row) * K + k0);  \
            ra[p] = make_uint2(pack_h2(av.x, av.y), pack_h2(av.z, av.w));   \
            rw[p] = make_uint2(pack_h2(wv.x, wv.y), pack_h2(wv.z, wv.w));   \
        }                                                                   \
    }

#define STTILE(BUF)                                                         \
    {                                                                       \
        uint32_t Abb = sbase + (BUF) * STAGE_BB;                            \
        uint32_t Bbb = Abb + ATILE_B;                                       \
        _Pragma("unroll") for (int p = 0; p < 8; p++) {                     \
            int row = lrow + p * 16;                                        \
            uint32_t off = row * ROWB + c4 * 8;                             \
            asm volatile("st.shared.v2.b32 [%0], {%1,%2};"                  \
                         :: "r"(Abb + off), "r"(ra[p].x), "r"(ra[p].y)      \
                         : "memory");                                       \
            asm volatile("st.shared.v2.b32 [%0], {%1,%2};"                  \
                         :: "r"(Bbb + off), "r"(rw[p].x), "r"(rw[p].y)      \
                         : "memory");                                       \
        }                                                                   \
    }

    LDTILE(it0);
    STTILE(0);
    __syncthreads();

    const int a_m = (lane & 7) + (lane & 8);
    const int a_koff = (lane >> 4) * 16;
    const int b_n = (lane & 7) + ((lane >> 4) & 1) * 8;
    const int b_koff = ((lane >> 3) & 1) * 16;

    int buf = 0;
    for (int it = 0; it < nt; ++it) {
        bool more = (it + 1 < nt);
        if (more) LDTILE(it0 + it + 1);

        uint32_t Ab = sbase + buf * STAGE_BB;
        uint32_t Bb = Ab + ATILE_B;
#pragma unroll
        for (int ks = 0; ks < 4; ks++) {
            int kbyte = ks * 32;
            uint32_t af[2][4];
#pragma unroll
            for (int mi = 0; mi < 2; mi++) {
                uint32_t addr = Ab + (wm + mi * 16 + a_m) * ROWB + kbyte + a_koff;
                LDSM_X4(af[mi][0], af[mi][1], af[mi][2], af[mi][3], addr);
            }
            uint32_t bf[8][2];
#pragma unroll
            for (int nj = 0; nj < 4; nj++) {
                uint32_t addr = Bb + (wn + nj * 16 + b_n) * ROWB + kbyte + b_koff;
                LDSM_X4(bf[2 * nj][0], bf[2 * nj][1],
                        bf[2 * nj + 1][0], bf[2 * nj + 1][1], addr);
            }
#pragma unroll
            for (int mi = 0; mi < 2; mi++)
#pragma unroll
                for (int ni = 0; ni < 8; ni++)
                    mma_f16(acc[mi][ni], af[mi], bf[ni]);
        }
        if (more) STTILE(buf ^ 1);
        __syncthreads();
        buf ^= 1;
    }

    const int g = lane >> 2, t = lane & 3;
    float* Pb = P + (size_t)blockIdx.y * NROW * N;
#pragma unroll
    for (int mi = 0; mi < 2; mi++) {
        int r0 = wm + mi * 16 + g;
#pragma unroll
        for (int ni = 0; ni < 8; ni++) {
            int c = bn + wn + ni * 8 + 2 * t;
            *(float2*)(Pb + (size_t)r0 * N + c) =
                make_float2(acc[mi][ni][0], acc[mi][ni][1]);
            *(float2*)(Pb + (size_t)(r0 + 8) * N + c) =
                make_float2(acc[mi][ni][2], acc[mi][ni][3]);
        }
    }
}

// ---------------- fused QKV reduce(+bias, S=S_QKV) + RoPE + K/V scatter ----------------
__global__ __launch_bounds__(256) void reduce_qkv_rope(
    const float* __restrict__ P, const float* __restrict__ bias,
    float* __restrict__ qkv, float* __restrict__ Kout, float* __restrict__ Vout,
    float* __restrict__ knew, float* __restrict__ vnew)
{
    __shared__ float srow[QKVD];
    int row = blockIdx.x;
    int b = row >> 4, t = row & 15, pos = TC + t;
    const int RV4 = QKVD / 4;
    const size_t SPLIT = (size_t)NROW * RV4;
    const float4* P4 = (const float4*)P;
    const float4* B4 = (const float4*)bias;

#pragma unroll
    for (int k = 0; k < 5; k++) {
        int i = threadIdx.x + k * 256;
        size_t off = (size_t)row * RV4 + i;
        float4 a = B4[i];
#pragma unroll
        for (int s = 0; s < S_QKV; s++) {
            float4 p = P4[off + (size_t)s * SPLIT];
            a.x += p.x; a.y += p.y; a.z += p.z; a.w += p.w;
        }
        *(float4*)&srow[i * 4] = a;
    }
    __syncthreads();

    const float NEG_L2T_32 = -0.537331431f;
    for (int p = threadIdx.x; p < 2048 + 256; p += 256) {
        bool isq = (p < 2048);
        int pp = isq ? p : p - 2048;
        int head = pp >> 5, j = pp & 31;
        int base = (isq ? head * 64 : HQ * Dh + head * 64);
        float invf = exp2f((float)j * NEG_L2T_32);
        float ang = (float)pos * invf;
        float c = cosf(ang), s = sinf(ang);
        float x1 = srow[base + j], x2 = srow[base + j + 32];
        float r1 = x1 * c - x2 * s;
        float r2 = x2 * c + x1 * s;
        if (isq) {
            qkv[(size_t)row * QKVD + base + j] = r1;
            qkv[(size_t)row * QKVD + base + j + 32] = r2;
        } else {
            size_t o = ((((size_t)b * TTOT) + pos) * HKV + head) * Dh;
            Kout[o + j] = r1;
            Kout[o + j + 32] = r2;
            size_t on = (((size_t)row * HKV) + head) * Dh;
            knew[on + j] = r1;
            knew[on + j + 32] = r2;
        }
    }
    for (int i = threadIdx.x; i < HKV * Dh; i += 256) {
        float v = srow[(HQ + HKV) * Dh + i];
        Vout[(((size_t)b * TTOT) + pos) * HKV * Dh + i] = v;
        vnew[(size_t)row * HKV * Dh + i] = v;
    }
}

// ---------------- OUT reduce: S_OUT splits + bias + residual ----------------
__global__ __launch_bounds__(256) void reduce_out_kernel(
    const float* __restrict__ P, const float* __restrict__ bias,
    const float* __restrict__ x, float* __restrict__ out)
{
    int i = blockIdx.x * 256 + threadIdx.x;
    const int TOT = NROW * HID / 4;
    const float4* P4 = (const float4*)P;
    float4 bb = ((const float4*)bias)[i & (HID / 4 - 1)];
    float4 rr = ((const float4*)x)[i];
    float4 a = make_float4(bb.x + rr.x, bb.y + rr.y, bb.z + rr.z, bb.w + rr.w);
#pragma unroll
    for (int s = 0; s < S_OUT; s++) {
        float4 p = P4[i + (size_t)s * TOT];
        a.x += p.x; a.y += p.y; a.z += p.z; a.w += p.w;
    }
    ((float4*)out)[i] = a;
}

// ---------------- windowed attention with sink ----------------
__global__ __launch_bounds__(256) void attn_kernel(
    const float* __restrict__ qkv,
    const float* __restrict__ cache_k, const float* __restrict__ cache_v,
    const float* __restrict__ knew, const float* __restrict__ vnew,
    const float* __restrict__ sinks, float* __restrict__ attn)
{
    int hkv = blockIdx.x;
    int t = blockIdx.y;
    int b = blockIdx.z;
    int row = b * Tq + t;
    int k0 = TC + t - WIN;

    __shared__ float sKV[NKEY * 65];
    __shared__ float sQ[QMULT * Dh];
    __shared__ float sW[QMULT * 132];

    int tid = threadIdx.x;
    int warp = tid >> 5, lane = tid & 31;

    for (int i = tid; i < QMULT * Dh; i += 256)
        sQ[i] = qkv[(size_t)row * QKVD + hkv * (QMULT * Dh) + i];

    for (int i = tid; i < NKEY * Dh; i += 256) {
        int j = i >> 6, d = i & 63;
        int kj = k0 + j;
        float v;
        if (kj < TC)
            v = cache_k[(((size_t)b * TC + kj) * HKV + hkv) * Dh + d];
        else
            v = knew[(((size_t)b * Tq + (kj - TC)) * HKV + hkv) * Dh + d];
        sKV[j * 65 + d] = v;
    }
    __syncthreads();

    float lgv[5];
    float mx = -INFINITY;
#pragma unroll
    for (int i = 0; i < 5; i++) {
        int j = lane + i * 32;
        float acc = -INFINITY;
        if (j < NKEY) {
            acc = 0.f;
            const float* qq = &sQ[warp * Dh];
            const float* kk = &sKV[j * 65];
#pragma unroll 8
            for (int d = 0; d < Dh; d++) acc = fmaf(qq[d], kk[d], acc);
            acc *= SM_SCALE;
        }
        lgv[i] = acc;
        mx = fmaxf(mx, acc);
    }
#pragma unroll
    for (int o = 16; o > 0; o >>= 1)
        mx = fmaxf(mx, __shfl_xor_sync(0xffffffffu, mx, o));
    float snk = sinks[hkv * QMULT + warp];
    mx = fmaxf(mx, snk);

    float se = 0.f;
#pragma unroll
    for (int i = 0; i < 5; i++) {
        int j = lane + i * 32;
        if (j < NKEY) {
            lgv[i] = expf(lgv[i] - mx);
            se += lgv[i];
        }
    }
#pragma unroll
    for (int o = 16; o > 0; o >>= 1)
        se += __shfl_xor_sync(0xffffffffu, se, o);
    float denom = se + expf(snk - mx);
    float rdenom = 1.f / denom;
#pragma unroll
    for (int i = 0; i < 5; i++) {
        int j = lane + i * 32;
        if (j < NKEY) sW[warp * 132 + j] = lgv[i] * rdenom;
    }
    __syncthreads();

    for (int i = tid; i < NKEY * Dh; i += 256) {
        int j = i >> 6, d = i & 63;
        int kj = k0 + j;
        float v;
        if (kj < TC)
            v = cache_v[(((size_t)b * TC + kj) * HKV + hkv) * Dh + d];
        else
            v = vnew[(((size_t)b * Tq + (kj - TC)) * HKV + hkv) * Dh + d];
        sKV[j * 65 + d] = v;
    }
    __syncthreads();

    float a0 = 0.f, a1 = 0.f;
#pragma unroll 4
    for (int j = 0; j < NKEY; j++) {
        float w = sW[warp * 132 + j];
        a0 = fmaf(w, sKV[j * 65 + lane], a0);
        a1 = fmaf(w, sKV[j * 65 + 32 + lane], a1);
    }
    size_t ob = (size_t)row * HID + (hkv * QMULT + warp) * Dh;
    attn[ob + lane] = a0;
    attn[ob + 32 + lane] = a1;
}

// ---------------- launch ----------------
extern "C" void kernel_launch(void* const* d_in, const int* in_sizes, int n_in,
                              void* d_out, int out_size)
{
    int sh = 0;
    if (n_in >= 10) sh = 1;
    else if (n_in == 9 && in_sizes[3] == 1) sh = 1;

    const float* x       = (const float*)d_in[0];
    const float* cache_k = (const float*)d_in[1];
    const float* cache_v = (const float*)d_in[2];
    const float* sinks   = (const float*)d_in[3 + sh];
    const float* norm_w  = (const float*)d_in[4 + sh];
    const float* qkv_w   = (const float*)d_in[5 + sh];
    const float* qkv_b   = (const float*)d_in[6 + sh];
    const float* out_w   = (const float*)d_in[7 + sh];
    const float* out_b   = (const float*)d_in[8 + sh];

    float* out  = (float*)d_out;
    float* Kout = out + OUT_ELEMS;
    float* Vout = Kout + KV_ELEMS;

    float *hp, *qkvp, *attnp, *partp, *knp, *vnp;
    cudaGetSymbolAddress((void**)&hp, g_h);
    cudaGetSymbolAddress((void**)&qkvp, g_qkv);
    cudaGetSymbolAddress((void**)&attnp, g_attn);
    cudaGetSymbolAddress((void**)&partp, g_part);
    cudaGetSymbolAddress((void**)&knp, g_knew);
    cudaGetSymbolAddress((void**)&vnp, g_vnew);

    static cudaStream_t s_copy = nullptr;
    static cudaEvent_t ev_fork = nullptr, ev_join = nullptr;
    static int inited = 0;
    if (!inited) {
        cudaStreamCreateWithFlags(&s_copy, cudaStreamNonBlocking);
        cudaEventCreateWithFlags(&ev_fork, cudaEventDisableTiming);
        cudaEventCreateWithFlags(&ev_join, cudaEventDisableTiming);
        cudaFuncSetAttribute(gemm_f16_splitk,
                             cudaFuncAttributeMaxDynamicSharedMemorySize,
                             2 * STAGE_BB);
        inited = 1;
    }
    const int smem_bytes = 2 * STAGE_BB;   // 73728

    // fork: K and V cache copies on side stream, small grids to co-reside
    cudaEventRecord(ev_fork, 0);
    cudaStreamWaitEvent(s_copy, ev_fork, 0);
    copy_one_kernel<<<CPY_CTAS, CPY_THREADS, 0, s_copy>>>(
        (const float4*)cache_k, (float4*)Kout);
    copy_one_kernel<<<CPY_CTAS, CPY_THREADS, 0, s_copy>>>(
        (const float4*)cache_v, (float4*)Vout);
    cudaEventRecord(ev_join, s_copy);

    // compute chain (gemm_qkv is the 4th launch -> profiled by ncu)
    rmsnorm_kernel<<<NROW, 256>>>(x, norm_w, hp);
    {
        dim3 grid(QKVD / 128, S_QKV);
        gemm_f16_splitk<<<grid, 256, smem_bytes>>>(hp, qkv_w, partp, QKVD, HID);
    }
    reduce_qkv_rope<<<NROW, 256>>>(partp, qkv_b, qkvp, Kout, Vout, knp, vnp);
    {
        dim3 grid(HKV, Tq, Bq);
        attn_kernel<<<grid, 256>>>(qkvp, cache_k, cache_v, knp, vnp, sinks, attnp);
    }
    {
        dim3 grid(HID / 128, S_OUT);
        gemm_f16_splitk<<<grid, 256, smem_bytes>>>(attnp, out_w, partp, HID, HID);
    }
    reduce_out_kernel<<<NROW * HID / 4 / 256, 256>>>(partp, out_b, x, out);

    cudaStreamWaitEvent(0, ev_join, 0);
}